// round 8
// baseline (speedup 1.0000x reference)
#include <cuda_runtime.h>
#include <cuda_bf16.h>
#include <cstdint>

// ---------------- problem constants ----------------
#define BATCH   16
#define HDIM    112
#define CCH     128
#define LTOK    (HDIM*HDIM)          // 12544
#define MTOK    (BATCH*LTOK)         // 200704
#define NHEAD   4
#define HD      32
#define NWIMG   256                  // windows per image (16x16)
#define BWIN    (BATCH*NWIMG)        // 4096
#define HIDDEN  512

// ---------------- scratch (device globals; no runtime alloc) ----------------
__device__ __align__(256) __nv_bfloat16 g_xw [(size_t)MTOK*CCH];
__device__ __align__(256) __nv_bfloat16 g_qkv[(size_t)MTOK*3*CCH];
__device__ __align__(256) __nv_bfloat16 g_o  [(size_t)MTOK*CCH];
__device__ __align__(256) float         g_x1 [(size_t)MTOK*CCH];
__device__ __align__(256) __nv_bfloat16 g_ln2[(size_t)MTOK*CCH];
__device__ __align__(256) __nv_bfloat16 g_wqkv[3*CCH*CCH];
__device__ __align__(256) __nv_bfloat16 g_wproj[CCH*CCH];
__device__ __align__(256) __nv_bfloat16 g_wfc1[HIDDEN*CCH];
__device__ __align__(256) __nv_bfloat16 g_wfc2[CCH*HIDDEN];
__device__ __align__(256) float g_comb[(size_t)NWIMG*NHEAD*2401];

// ---------------- helpers ----------------
__device__ __forceinline__ int tok_map(int r){
    int widx = r / 49, n = r - widx*49;
    int b  = widx >> 8, w = widx & 255;
    int wi = w >> 4,   wj = w & 15;
    int ti = n / 7,    tj = n - ti*7;
    int i = wi*7 + ti + 3; if (i >= HDIM) i -= HDIM;
    int j = wj*7 + tj + 3; if (j >= HDIM) j -= HDIM;
    return (b*HDIM + i)*HDIM + j;
}

__device__ __forceinline__ float gelu_exact(float v){
    return 0.5f * v * (1.0f + erff(v * 0.70710678118654752f));
}

__device__ __forceinline__ void ldmx4(uint32_t r[4], uint32_t a){
    asm volatile("ldmatrix.sync.aligned.m8n8.x4.shared.b16 {%0,%1,%2,%3}, [%4];"
                 : "=r"(r[0]), "=r"(r[1]), "=r"(r[2]), "=r"(r[3]) : "r"(a));
}
__device__ __forceinline__ void ldmx4t(uint32_t r[4], uint32_t a){
    asm volatile("ldmatrix.sync.aligned.m8n8.x4.trans.shared.b16 {%0,%1,%2,%3}, [%4];"
                 : "=r"(r[0]), "=r"(r[1]), "=r"(r[2]), "=r"(r[3]) : "r"(a));
}
__device__ __forceinline__ void mma_bf16(float* c, const uint32_t a[4], uint32_t b0, uint32_t b1){
    asm volatile("mma.sync.aligned.m16n8k16.row.col.f32.bf16.bf16.f32 "
                 "{%0,%1,%2,%3}, {%4,%5,%6,%7}, {%8,%9}, {%0,%1,%2,%3};"
                 : "+f"(c[0]), "+f"(c[1]), "+f"(c[2]), "+f"(c[3])
                 : "r"(a[0]), "r"(a[1]), "r"(a[2]), "r"(a[3]), "r"(b0), "r"(b1));
}
__device__ __forceinline__ void cp16(void* dst, const void* src){
    uint32_t d = (uint32_t)__cvta_generic_to_shared(dst);
    asm volatile("cp.async.cg.shared.global [%0], [%1], 16;" :: "r"(d), "l"(src));
}
__device__ __forceinline__ void cp16z(void* dst, const void* src, int sz){
    uint32_t d = (uint32_t)__cvta_generic_to_shared(dst);
    asm volatile("cp.async.cg.shared.global [%0], [%1], 16, %2;" :: "r"(d), "l"(src), "r"(sz));
}
__device__ __forceinline__ uint32_t packbf(float x, float y){
    __nv_bfloat162 t = __floats2bfloat162_rn(x, y);
    return *reinterpret_cast<uint32_t*>(&t);
}

// ---------------- kernel: weight conversion fp32 -> bf16 ----------------
__global__ void cvt_weights(const float* __restrict__ qkvw, const float* __restrict__ projw,
                            const float* __restrict__ fc1w, const float* __restrict__ fc2w){
    int i = blockIdx.x*blockDim.x + threadIdx.x;
    if (i < 3*CCH*CCH)  g_wqkv[i]  = __float2bfloat16(qkvw[i]);
    if (i < CCH*CCH)    g_wproj[i] = __float2bfloat16(projw[i]);
    if (i < HIDDEN*CCH){ g_wfc1[i] = __float2bfloat16(fc1w[i]);
                         g_wfc2[i] = __float2bfloat16(fc2w[i]); }
}

// ---------------- kernel: combined mask + rel-pos bias table ----------------
__global__ void comb_kernel(const float* __restrict__ mask, const float* __restrict__ table){
    int idx = blockIdx.x*256 + threadIdx.x;
    if (idx >= NWIMG*NHEAD*2401) return;
    int nm = idx % 2401, wh = idx / 2401;
    int h = wh & 3, w = wh >> 2;
    int n = nm / 49, m = nm - n*49;
    int ni = n/7, nj = n - ni*7, mi = m/7, mj = m - mi*7;
    g_comb[idx] = mask[w*2401 + nm] + table[((ni-mi+6)*13 + (nj-mj+6))*4 + h];
}

// ---------------- kernel: LayerNorm1, warp-per-row, gather permutation ----------------
__global__ __launch_bounds__(256) void ln1_kernel(const float* __restrict__ xin,
                                                  const float* __restrict__ g,
                                                  const float* __restrict__ b){
    int lane = threadIdx.x & 31, warp = threadIdx.x >> 5;
    int r = blockIdx.x*8 + warp;
    int p = tok_map(r);
    float4 v = *reinterpret_cast<const float4*>(xin + (size_t)p*CCH + lane*4);
    float s = v.x + v.y + v.z + v.w;
    float q = v.x*v.x + v.y*v.y + v.z*v.z + v.w*v.w;
    #pragma unroll
    for (int o = 16; o > 0; o >>= 1){
        s += __shfl_xor_sync(0xffffffffu, s, o);
        q += __shfl_xor_sync(0xffffffffu, q, o);
    }
    float mean = s * (1.0f/CCH);
    float inv  = rsqrtf(q * (1.0f/CCH) - mean*mean + 1e-5f);
    float4 gg = *reinterpret_cast<const float4*>(g + lane*4);
    float4 bb = *reinterpret_cast<const float4*>(b + lane*4);
    __nv_bfloat162 o0 = __floats2bfloat162_rn((v.x-mean)*inv*gg.x + bb.x,
                                              (v.y-mean)*inv*gg.y + bb.y);
    __nv_bfloat162 o1 = __floats2bfloat162_rn((v.z-mean)*inv*gg.z + bb.z,
                                              (v.w-mean)*inv*gg.w + bb.w);
    uint2 st; st.x = *reinterpret_cast<uint32_t*>(&o0); st.y = *reinterpret_cast<uint32_t*>(&o1);
    *reinterpret_cast<uint2*>(g_xw + (size_t)r*CCH + lane*4) = st;
}

// ---------------- kernel: tensor-core windowed attention ----------------
__global__ __launch_bounds__(256) void attn_mma_kernel(){
    int widx  = blockIdx.x >> 1;
    int hpair = blockIdx.x & 1;

    __shared__ uint4 sQKV[6][64][4];

    int tid = threadIdx.x, lane = tid & 31, warp = tid >> 5;
    int hloc = warp >> 2, strip = warp & 3;
    int hglb = hpair*2 + hloc;

    // async load with zero-fill for pad rows
    #pragma unroll
    for (int j = 0; j < 6; j++){
        int i  = tid + 256*j;
        int hm = i >> 8;
        int hl = hm / 3, mat = hm % 3;
        int r  = (i >> 2) & 63;
        int c  = i & 3;
        const void* src = g_qkv + ((size_t)(widx*49 + (r < 49 ? r : 0)))*384
                          + mat*128 + (hpair*2 + hl)*32 + c*8;
        cp16z(&sQKV[hm][r][c ^ ((r >> 1) & 3)], src, (r < 49) ? 16 : 0);
    }
    asm volatile("cp.async.commit_group;");
    asm volatile("cp.async.wait_group 0;");
    __syncthreads();

    const uint4* Qb = &sQKV[hloc*3 + 0][0][0];
    const uint4* Kb = &sQKV[hloc*3 + 1][0][0];
    const uint4* Vb = &sQKV[hloc*3 + 2][0][0];

    auto swa = [](const uint4* base, int row, int chunk) -> uint32_t {
        return (uint32_t)__cvta_generic_to_shared(base + row*4 + (chunk ^ ((row >> 1) & 3)));
    };

    float sacc[8][4];
    #pragma unroll
    for (int i = 0; i < 8; i++){ sacc[i][0]=0.f; sacc[i][1]=0.f; sacc[i][2]=0.f; sacc[i][3]=0.f; }

    #pragma unroll
    for (int kt = 0; kt < 2; kt++){
        uint32_t aq[4];
        ldmx4(aq, swa(Qb, strip*16 + (lane & 15), kt*2 + (lane >> 4)));
        #pragma unroll
        for (int p = 0; p < 4; p++){
            uint32_t kb[4];
            ldmx4(kb, swa(Kb, p*16 + (lane & 15), kt*2 + (lane >> 4)));
            mma_bf16(sacc[2*p],   aq, kb[0], kb[2]);
            mma_bf16(sacc[2*p+1], aq, kb[1], kb[3]);
        }
    }

    const float scale = 0.17677669529663687f;
    int l4 = lane >> 2, c2 = (lane & 3)*2;
    int r0 = strip*16 + l4;
    const float* crow = g_comb + ((size_t)(widx & 255)*4 + hglb)*2401;
    bool rv[2]; int rm[2];
    #pragma unroll
    for (int i = 0; i < 2; i++){
        int r = r0 + i*8;
        rv[i] = (r < 49);
        rm[i] = r*49;
    }

    #pragma unroll
    for (int nt = 0; nt < 8; nt++){
        #pragma unroll
        for (int jc = 0; jc < 2; jc++){
            int col = nt*8 + c2 + jc;
            bool cv = (col < 49);
            #pragma unroll
            for (int i = 0; i < 2; i++){
                float v = -1e30f;
                if (cv && rv[i])
                    v = sacc[nt][i*2+jc]*scale + crow[rm[i] + col];
                sacc[nt][i*2+jc] = v;
            }
        }
    }

    float mx[2] = {-1e30f, -1e30f};
    #pragma unroll
    for (int nt = 0; nt < 8; nt++)
        #pragma unroll
        for (int j = 0; j < 4; j++) mx[j>>1] = fmaxf(mx[j>>1], sacc[nt][j]);
    #pragma unroll
    for (int i = 0; i < 2; i++){
        mx[i] = fmaxf(mx[i], __shfl_xor_sync(0xffffffffu, mx[i], 1));
        mx[i] = fmaxf(mx[i], __shfl_xor_sync(0xffffffffu, mx[i], 2));
    }
    float sum[2] = {0.f, 0.f};
    #pragma unroll
    for (int nt = 0; nt < 8; nt++)
        #pragma unroll
        for (int j = 0; j < 4; j++){
            float e = __expf(sacc[nt][j] - mx[j>>1]);
            sacc[nt][j] = e;
            sum[j>>1] += e;
        }
    #pragma unroll
    for (int i = 0; i < 2; i++){
        sum[i] += __shfl_xor_sync(0xffffffffu, sum[i], 1);
        sum[i] += __shfl_xor_sync(0xffffffffu, sum[i], 2);
    }
    float inv[2] = {1.0f/sum[0], 1.0f/sum[1]};

    float oacc[4][4];
    #pragma unroll
    for (int i = 0; i < 4; i++){ oacc[i][0]=0.f; oacc[i][1]=0.f; oacc[i][2]=0.f; oacc[i][3]=0.f; }

    #pragma unroll
    for (int kt2 = 0; kt2 < 4; kt2++){
        uint32_t pa[4];
        pa[0] = packbf(sacc[2*kt2][0],   sacc[2*kt2][1]);
        pa[1] = packbf(sacc[2*kt2][2],   sacc[2*kt2][3]);
        pa[2] = packbf(sacc[2*kt2+1][0], sacc[2*kt2+1][1]);
        pa[3] = packbf(sacc[2*kt2+1][2], sacc[2*kt2+1][3]);
        #pragma unroll
        for (int half = 0; half < 2; half++){
            uint32_t vb[4];
            ldmx4t(vb, swa(Vb, kt2*16 + (lane & 15), half*2 + (lane >> 4)));
            mma_bf16(oacc[2*half],   pa, vb[0], vb[1]);
            mma_bf16(oacc[2*half+1], pa, vb[2], vb[3]);
        }
    }

    #pragma unroll
    for (int i = 0; i < 2; i++){
        int row = r0 + i*8;
        if (row < 49){
            size_t ro = ((size_t)(widx*49 + row))*CCH + hglb*HD;
            #pragma unroll
            for (int nt = 0; nt < 4; nt++){
                __nv_bfloat162 t = __floats2bfloat162_rn(oacc[nt][i*2]*inv[i],
                                                         oacc[nt][i*2+1]*inv[i]);
                *reinterpret_cast<__nv_bfloat162*>(g_o + ro + nt*8 + c2) = t;
            }
        }
    }
}

// ---------------- kernel: K=128 GEMM (qkv / proj), single-stage full-K ----------------
// EPI 0: QKV  -> bf16 g_qkv
// EPI 2: PROJ -> scatter + x residual -> g_x1 AND fused LN2 -> g_ln2
extern __shared__ __align__(16) char smem_raw[];

template<int EPI>
__launch_bounds__(256)
__global__ void gemm_kernel(const float* __restrict__ bias,
                            const float* __restrict__ resid,
                            const float* __restrict__ g2,
                            const float* __restrict__ b2){
    constexpr int LDO = (EPI == 0) ? 384 : 128;
    const __nv_bfloat16* A = (EPI == 0) ? g_xw : g_o;
    const __nv_bfloat16* W = (EPI == 0) ? g_wqkv : g_wproj;

    uint4* sA = reinterpret_cast<uint4*>(smem_raw);
    uint4* sB = sA + 2048;

    int tid = threadIdx.x, lane = tid & 31, warp = tid >> 5;
    int wm = warp >> 2, wn = warp & 3;
    int bm = blockIdx.x*128, bn = blockIdx.y*128;

    float acc[4][4][4];
    #pragma unroll
    for (int i = 0; i < 4; i++)
        #pragma unroll
        for (int j = 0; j < 4; j++)
            #pragma unroll
            for (int k = 0; k < 4; k++) acc[i][j][k] = 0.f;

    const __nv_bfloat16* Ag = A + (size_t)bm*128;
    const __nv_bfloat16* Wg = W + (size_t)bn*128;

    #pragma unroll
    for (int j = 0; j < 8; j++){
        int idx = tid + 256*j;
        int r = idx >> 4, u = idx & 15;
        int ph = r*16 + (u ^ (r & 7));
        cp16(sA + ph, Ag + (size_t)r*128 + u*8);
        cp16(sB + ph, Wg + (size_t)r*128 + u*8);
    }
    asm volatile("cp.async.commit_group;");
    asm volatile("cp.async.wait_group 0;");
    __syncthreads();

    auto sw = [](const uint4* base, int row, int unit) -> uint32_t {
        return (uint32_t)__cvta_generic_to_shared(base + row*16 + (unit ^ (row & 7)));
    };
    int arow = (lane & 15), aun = (lane >> 4);
    int brow = (lane & 7) + ((lane >> 4) << 3);
    int bun  = (lane >> 3) & 1;

    #pragma unroll
    for (int ks = 0; ks < 8; ks++){
        uint32_t bfr[2][4];
        ldmx4(bfr[0], sw(sB, wn*32 + brow,      ks*2 + bun));
        ldmx4(bfr[1], sw(sB, wn*32 + brow + 16, ks*2 + bun));
        #pragma unroll
        for (int mt = 0; mt < 4; mt++){
            uint32_t af[4];
            ldmx4(af, sw(sA, wm*64 + mt*16 + arow, ks*2 + aun));
            mma_bf16(acc[mt][0], af, bfr[0][0], bfr[0][1]);
            mma_bf16(acc[mt][1], af, bfr[0][2], bfr[0][3]);
            mma_bf16(acc[mt][2], af, bfr[1][0], bfr[1][1]);
            mma_bf16(acc[mt][3], af, bfr[1][2], bfr[1][3]);
        }
    }

    int l4 = lane >> 2, c2 = (lane & 3)*2;

    if constexpr (EPI == 2){
        __syncthreads();
        float* sred = reinterpret_cast<float*>(smem_raw);
        #pragma unroll
        for (int mt = 0; mt < 4; mt++){
            #pragma unroll
            for (int half = 0; half < 2; half++){
                int rloc = wm*64 + mt*16 + l4 + half*8;
                int gm = bm + rloc;
                int p = tok_map(gm);
                float s = 0.f, q = 0.f;
                #pragma unroll
                for (int nt = 0; nt < 4; nt++){
                    int gn = wn*32 + nt*8 + c2;
                    float2 xr = *reinterpret_cast<const float2*>(resid + (size_t)p*CCH + gn);
                    float v0 = acc[mt][nt][half*2+0] + bias[gn]   + xr.x;
                    float v1 = acc[mt][nt][half*2+1] + bias[gn+1] + xr.y;
                    acc[mt][nt][half*2+0] = v0;
                    acc[mt][nt][half*2+1] = v1;
                    float2 t; t.x = v0; t.y = v1;
                    *reinterpret_cast<float2*>(g_x1 + (size_t)p*CCH + gn) = t;
                    s += v0 + v1; q += v0*v0 + v1*v1;
                }
                s += __shfl_xor_sync(0xffffffffu, s, 1);
                s += __shfl_xor_sync(0xffffffffu, s, 2);
                q += __shfl_xor_sync(0xffffffffu, q, 1);
                q += __shfl_xor_sync(0xffffffffu, q, 2);
                if ((lane & 3) == 0){
                    sred[rloc*8 + wn]     = s;
                    sred[rloc*8 + 4 + wn] = q;
                }
            }
        }
        __syncthreads();
        #pragma unroll
        for (int mt = 0; mt < 4; mt++){
            #pragma unroll
            for (int half = 0; half < 2; half++){
                int rloc = wm*64 + mt*16 + l4 + half*8;
                int gm = bm + rloc;
                int p = tok_map(gm);
                float s = sred[rloc*8+0] + sred[rloc*8+1] + sred[rloc*8+2] + sred[rloc*8+3];
                float q = sred[rloc*8+4] + sred[rloc*8+5] + sred[rloc*8+6] + sred[rloc*8+7];
                float mean = s * (1.0f/CCH);
                float var  = q * (1.0f/CCH) - mean*mean;
                float inv  = rsqrtf(var + 1e-5f);
                #pragma unroll
                for (int nt = 0; nt < 4; nt++){
                    int gn = wn*32 + nt*8 + c2;
                    float v0 = (acc[mt][nt][half*2+0] - mean)*inv*g2[gn]   + b2[gn];
                    float v1 = (acc[mt][nt][half*2+1] - mean)*inv*g2[gn+1] + b2[gn+1];
                    *reinterpret_cast<__nv_bfloat162*>(g_ln2 + (size_t)p*CCH + gn) =
                        __floats2bfloat162_rn(v0, v1);
                }
            }
        }
    } else {
        #pragma unroll
        for (int mt = 0; mt < 4; mt++){
            int gmb = bm + wm*64 + mt*16 + l4;
            #pragma unroll
            for (int nt = 0; nt < 4; nt++){
                int gn = bn + wn*32 + nt*8 + c2;
                float bv0 = bias[gn], bv1 = bias[gn+1];
                #pragma unroll
                for (int half = 0; half < 2; half++){
                    int gm = gmb + half*8;
                    *reinterpret_cast<__nv_bfloat162*>(g_qkv + (size_t)gm*LDO + gn) =
                        __floats2bfloat162_rn(acc[mt][nt][half*2+0] + bv0,
                                              acc[mt][nt][half*2+1] + bv1);
                }
            }
        }
    }
}

// ---------------- kernel: fused MLP  out = x1 + fc2(gelu(fc1(ln2))) ----------------
// One CTA = 128 tokens. Loop over 4 hidden chunks of 128; f1 chunk lives in smem only.
#define MLP_SMEM 196608
__launch_bounds__(256)
__global__ void mlp_kernel(const float* __restrict__ b1, const float* __restrict__ b2,
                           float* __restrict__ outf){
    uint4* sA  = reinterpret_cast<uint4*>(smem_raw);       // 2048 : ln2 tile
    uint4* sF  = sA + 2048;                                 // 2048 : f1 chunk (bf16)
    uint4* sW1[2] = { sA + 4096, sA + 6144 };
    uint4* sW2[2] = { sA + 8192, sA + 10240 };

    int tid = threadIdx.x, lane = tid & 31, warp = tid >> 5;
    int wm = warp >> 2, wn = warp & 3;
    int bm = blockIdx.x*128;

    auto sw = [](const uint4* base, int row, int unit) -> uint32_t {
        return (uint32_t)__cvta_generic_to_shared(base + row*16 + (unit ^ (row & 7)));
    };

    auto stageW = [&](int nb, int s){
        const __nv_bfloat16* W1g = g_wfc1 + (size_t)nb*128*128;        // contiguous rows
        const __nv_bfloat16* W2g = g_wfc2 + nb*128;                    // k-slice, row stride 512
        #pragma unroll
        for (int j = 0; j < 8; j++){
            int idx = tid + 256*j;
            int r = idx >> 4, u = idx & 15;
            int ph = r*16 + (u ^ (r & 7));
            cp16(sW1[s] + ph, W1g + (size_t)r*128 + u*8);
            cp16(sW2[s] + ph, W2g + (size_t)r*512 + u*8);
        }
    };

    // stage A + chunk0 in one group
    {
        const __nv_bfloat16* Ag = g_ln2 + (size_t)bm*128;
        #pragma unroll
        for (int j = 0; j < 8; j++){
            int idx = tid + 256*j;
            int r = idx >> 4, u = idx & 15;
            cp16(sA + r*16 + (u ^ (r & 7)), Ag + (size_t)r*128 + u*8);
        }
        stageW(0, 0);
        asm volatile("cp.async.commit_group;");
    }

    float f2[4][4][4];
    #pragma unroll
    for (int i = 0; i < 4; i++)
        #pragma unroll
        for (int j = 0; j < 4; j++)
            #pragma unroll
            for (int k = 0; k < 4; k++) f2[i][j][k] = 0.f;

    int arow = (lane & 15), aun = (lane >> 4);
    int brow = (lane & 7) + ((lane >> 4) << 3);
    int bun  = (lane >> 3) & 1;
    int l4 = lane >> 2, c2 = (lane & 3)*2;
    uint32_t sfBase = (uint32_t)__cvta_generic_to_shared(sF);

    #pragma unroll
    for (int nb = 0; nb < 4; nb++){
        if (nb + 1 < 4){
            stageW(nb + 1, (nb + 1) & 1);
            asm volatile("cp.async.commit_group;");
            asm volatile("cp.async.wait_group 1;");
        } else {
            asm volatile("cp.async.wait_group 0;");
        }
        __syncthreads();

        // f1 chunk = A @ W1chunk^T
        float f1[4][4][4];
        #pragma unroll
        for (int i = 0; i < 4; i++)
            #pragma unroll
            for (int j = 0; j < 4; j++)
                #pragma unroll
                for (int k = 0; k < 4; k++) f1[i][j][k] = 0.f;

        const uint4* w1 = sW1[nb & 1];
        #pragma unroll
        for (int ks = 0; ks < 8; ks++){
            uint32_t bfr[2][4];
            ldmx4(bfr[0], sw(w1, wn*32 + brow,      ks*2 + bun));
            ldmx4(bfr[1], sw(w1, wn*32 + brow + 16, ks*2 + bun));
            #pragma unroll
            for (int mt = 0; mt < 4; mt++){
                uint32_t af[4];
                ldmx4(af, sw(sA, wm*64 + mt*16 + arow, ks*2 + aun));
                mma_bf16(f1[mt][0], af, bfr[0][0], bfr[0][1]);
                mma_bf16(f1[mt][1], af, bfr[0][2], bfr[0][3]);
                mma_bf16(f1[mt][2], af, bfr[1][0], bfr[1][1]);
                mma_bf16(f1[mt][3], af, bfr[1][2], bfr[1][3]);
            }
        }

        // bias + gelu -> bf16 into sF (swizzled like an A tile)
        #pragma unroll
        for (int mt = 0; mt < 4; mt++){
            #pragma unroll
            for (int nt = 0; nt < 4; nt++){
                int gn = nb*128 + wn*32 + nt*8 + c2;
                float bv0 = b1[gn], bv1 = b1[gn+1];
                #pragma unroll
                for (int half = 0; half < 2; half++){
                    int row = wm*64 + mt*16 + l4 + half*8;
                    uint32_t v = packbf(gelu_exact(f1[mt][nt][half*2+0] + bv0),
                                        gelu_exact(f1[mt][nt][half*2+1] + bv1));
                    uint32_t addr = sfBase + row*256 + (((wn*4+nt) ^ (row & 7)) << 4) + c2*2;
                    asm volatile("st.shared.b32 [%0], %1;" :: "r"(addr), "r"(v));
                }
            }
        }
        __syncthreads();

        // f2 += F @ W2chunk^T
        const uint4* w2 = sW2[nb & 1];
        #pragma unroll
        for (int ks = 0; ks < 8; ks++){
            uint32_t bfr[2][4];
            ldmx4(bfr[0], sw(w2, wn*32 + brow,      ks*2 + bun));
            ldmx4(bfr[1], sw(w2, wn*32 + brow + 16, ks*2 + bun));
            #pragma unroll
            for (int mt = 0; mt < 4; mt++){
                uint32_t af[4];
                ldmx4(af, sw(sF, wm*64 + mt*16 + arow, ks*2 + aun));
                mma_bf16(f2[mt][0], af, bfr[0][0], bfr[0][1]);
                mma_bf16(f2[mt][1], af, bfr[0][2], bfr[0][3]);
                mma_bf16(f2[mt][2], af, bfr[1][0], bfr[1][1]);
                mma_bf16(f2[mt][3], af, bfr[1][2], bfr[1][3]);
            }
        }
        __syncthreads();
    }

    // epilogue: + fc2 bias + x1 residual -> out (fp32)
    #pragma unroll
    for (int mt = 0; mt < 4; mt++){
        int gmb = bm + wm*64 + mt*16 + l4;
        #pragma unroll
        for (int nt = 0; nt < 4; nt++){
            int gn = wn*32 + nt*8 + c2;
            float bv0 = b2[gn], bv1 = b2[gn+1];
            #pragma unroll
            for (int half = 0; half < 2; half++){
                int gm = gmb + half*8;
                size_t o = (size_t)gm*CCH + gn;
                float2 xr = *reinterpret_cast<const float2*>(g_x1 + o);
                float2 t;
                t.x = xr.x + f2[mt][nt][half*2+0] + bv0;
                t.y = xr.y + f2[mt][nt][half*2+1] + bv1;
                *reinterpret_cast<float2*>(outf + o) = t;
            }
        }
    }
}

#define G128_SMEM 65536

// ---------------- host launch ----------------
extern "C" void kernel_launch(void* const* d_in, const int* in_sizes, int n_in,
                              void* d_out, int out_size){
    int off = (n_in >= 17) ? 2 : 0;
    const float* x     = (const float*)d_in[0];
    const float* mask  = (const float*)d_in[1 + off];
    const float* ln1g  = (const float*)d_in[2 + off];
    const float* ln1b  = (const float*)d_in[3 + off];
    const float* qkvw  = (const float*)d_in[4 + off];
    const float* qkvb  = (const float*)d_in[5 + off];
    const float* relt  = (const float*)d_in[6 + off];
    const float* projw = (const float*)d_in[7 + off];
    const float* projb = (const float*)d_in[8 + off];
    const float* ln2g  = (const float*)d_in[9 + off];
    const float* ln2b  = (const float*)d_in[10 + off];
    const float* fc1w  = (const float*)d_in[11 + off];
    const float* fc1b  = (const float*)d_in[12 + off];
    const float* fc2w  = (const float*)d_in[13 + off];
    const float* fc2b  = (const float*)d_in[14 + off];
    float* out = (float*)d_out;

    cudaFuncSetAttribute(gemm_kernel<0>, cudaFuncAttributeMaxDynamicSharedMemorySize, G128_SMEM);
    cudaFuncSetAttribute(gemm_kernel<2>, cudaFuncAttributeMaxDynamicSharedMemorySize, G128_SMEM);
    cudaFuncSetAttribute(mlp_kernel,     cudaFuncAttributeMaxDynamicSharedMemorySize, MLP_SMEM);

    cvt_weights<<<256, 256>>>(qkvw, projw, fc1w, fc2w);
    comb_kernel<<<(NWIMG*NHEAD*2401 + 255)/256, 256>>>(mask, relt);
    ln1_kernel<<<MTOK/8, 256>>>(x, ln1g, ln1b);
    gemm_kernel<0><<<dim3(MTOK/128, 3), 256, G128_SMEM>>>(qkvb, nullptr, nullptr, nullptr);
    attn_mma_kernel<<<BWIN*2, 256>>>();
    gemm_kernel<2><<<dim3(MTOK/128, 1), 256, G128_SMEM>>>(projb, x, ln2g, ln2b);
    mlp_kernel<<<MTOK/128, 256, MLP_SMEM>>>(fc1b, fc2b, out);
}

// round 11
// speedup vs baseline: 1.2657x; 1.2657x over previous
#include <cuda_runtime.h>
#include <cuda_bf16.h>
#include <cstdint>

// ---------------- problem constants ----------------
#define BATCH   16
#define HDIM    112
#define CCH     128
#define LTOK    (HDIM*HDIM)          // 12544
#define MTOK    (BATCH*LTOK)         // 200704
#define NHEAD   4
#define HD      32
#define NWIMG   256
#define BWIN    (BATCH*NWIMG)        // 4096
#define HIDDEN  512

// ---------------- scratch (device globals; no runtime alloc) ----------------
__device__ __align__(256) __nv_bfloat16 g_xw [(size_t)MTOK*CCH];
__device__ __align__(256) __nv_bfloat16 g_qkv[(size_t)MTOK*3*CCH];
__device__ __align__(256) __nv_bfloat16 g_o  [(size_t)MTOK*CCH];
__device__ __align__(256) float         g_x1 [(size_t)MTOK*CCH];
__device__ __align__(256) __nv_bfloat16 g_ln2[(size_t)MTOK*CCH];
__device__ __align__(256) __nv_bfloat16 g_f1 [(size_t)MTOK*HIDDEN];
__device__ __align__(256) __nv_bfloat16 g_wqkv[3*CCH*CCH];
__device__ __align__(256) __nv_bfloat16 g_wproj[CCH*CCH];
__device__ __align__(256) __nv_bfloat16 g_wfc1[HIDDEN*CCH];
__device__ __align__(256) __nv_bfloat16 g_wfc2[CCH*HIDDEN];
__device__ __align__(256) float g_comb[(size_t)NWIMG*NHEAD*2401];

// ---------------- helpers ----------------
__device__ __forceinline__ int tok_map(int r){
    int widx = r / 49, n = r - widx*49;
    int b  = widx >> 8, w = widx & 255;
    int wi = w >> 4,   wj = w & 15;
    int ti = n / 7,    tj = n - ti*7;
    int i = wi*7 + ti + 3; if (i >= HDIM) i -= HDIM;
    int j = wj*7 + tj + 3; if (j >= HDIM) j -= HDIM;
    return (b*HDIM + i)*HDIM + j;
}

__device__ __forceinline__ float gelu_exact(float v){
    return 0.5f * v * (1.0f + erff(v * 0.70710678118654752f));
}

__device__ __forceinline__ void ldmx4(uint32_t r[4], uint32_t a){
    asm volatile("ldmatrix.sync.aligned.m8n8.x4.shared.b16 {%0,%1,%2,%3}, [%4];"
                 : "=r"(r[0]), "=r"(r[1]), "=r"(r[2]), "=r"(r[3]) : "r"(a));
}
__device__ __forceinline__ void ldmx4t(uint32_t r[4], uint32_t a){
    asm volatile("ldmatrix.sync.aligned.m8n8.x4.trans.shared.b16 {%0,%1,%2,%3}, [%4];"
                 : "=r"(r[0]), "=r"(r[1]), "=r"(r[2]), "=r"(r[3]) : "r"(a));
}
__device__ __forceinline__ void mma_bf16(float* c, const uint32_t a[4], uint32_t b0, uint32_t b1){
    asm volatile("mma.sync.aligned.m16n8k16.row.col.f32.bf16.bf16.f32 "
                 "{%0,%1,%2,%3}, {%4,%5,%6,%7}, {%8,%9}, {%0,%1,%2,%3};"
                 : "+f"(c[0]), "+f"(c[1]), "+f"(c[2]), "+f"(c[3])
                 : "r"(a[0]), "r"(a[1]), "r"(a[2]), "r"(a[3]), "r"(b0), "r"(b1));
}
__device__ __forceinline__ void cp16(void* dst, const void* src){
    uint32_t d = (uint32_t)__cvta_generic_to_shared(dst);
    asm volatile("cp.async.cg.shared.global [%0], [%1], 16;" :: "r"(d), "l"(src));
}
__device__ __forceinline__ uint32_t packbf(float x, float y){
    __nv_bfloat162 t = __floats2bfloat162_rn(x, y);
    return *reinterpret_cast<uint32_t*>(&t);
}

// ---------------- kernel: weight conversion fp32 -> bf16 ----------------
__global__ void cvt_weights(const float* __restrict__ qkvw, const float* __restrict__ projw,
                            const float* __restrict__ fc1w, const float* __restrict__ fc2w){
    int i = blockIdx.x*blockDim.x + threadIdx.x;
    if (i < 3*CCH*CCH)  g_wqkv[i]  = __float2bfloat16(qkvw[i]);
    if (i < CCH*CCH)    g_wproj[i] = __float2bfloat16(projw[i]);
    if (i < HIDDEN*CCH){ g_wfc1[i] = __float2bfloat16(fc1w[i]);
                         g_wfc2[i] = __float2bfloat16(fc2w[i]); }
}

// ---------------- kernel: combined mask + rel-pos bias table ----------------
__global__ void comb_kernel(const float* __restrict__ mask, const float* __restrict__ table){
    int idx = blockIdx.x*256 + threadIdx.x;
    if (idx >= NWIMG*NHEAD*2401) return;
    int nm = idx % 2401, wh = idx / 2401;
    int h = wh & 3, w = wh >> 2;
    int n = nm / 49, m = nm - n*49;
    int ni = n/7, nj = n - ni*7, mi = m/7, mj = m - mi*7;
    g_comb[idx] = mask[w*2401 + nm] + table[((ni-mi+6)*13 + (nj-mj+6))*4 + h];
}

// ---------------- kernel: LayerNorm1, warp-per-row, gather permutation ----------------
__global__ __launch_bounds__(256) void ln1_kernel(const float* __restrict__ xin,
                                                  const float* __restrict__ g,
                                                  const float* __restrict__ b){
    int lane = threadIdx.x & 31, warp = threadIdx.x >> 5;
    int r = blockIdx.x*8 + warp;
    int p = tok_map(r);
    float4 v = *reinterpret_cast<const float4*>(xin + (size_t)p*CCH + lane*4);
    float s = v.x + v.y + v.z + v.w;
    float q = v.x*v.x + v.y*v.y + v.z*v.z + v.w*v.w;
    #pragma unroll
    for (int o = 16; o > 0; o >>= 1){
        s += __shfl_xor_sync(0xffffffffu, s, o);
        q += __shfl_xor_sync(0xffffffffu, q, o);
    }
    float mean = s * (1.0f/CCH);
    float inv  = rsqrtf(q * (1.0f/CCH) - mean*mean + 1e-5f);
    float4 gg = *reinterpret_cast<const float4*>(g + lane*4);
    float4 bb = *reinterpret_cast<const float4*>(b + lane*4);
    __nv_bfloat162 o0 = __floats2bfloat162_rn((v.x-mean)*inv*gg.x + bb.x,
                                              (v.y-mean)*inv*gg.y + bb.y);
    __nv_bfloat162 o1 = __floats2bfloat162_rn((v.z-mean)*inv*gg.z + bb.z,
                                              (v.w-mean)*inv*gg.w + bb.w);
    uint2 st; st.x = *reinterpret_cast<uint32_t*>(&o0); st.y = *reinterpret_cast<uint32_t*>(&o1);
    *reinterpret_cast<uint2*>(g_xw + (size_t)r*CCH + lane*4) = st;
}

// ---------------- kernel: tensor-core windowed attention (R6 version) ----------------
__global__ __launch_bounds__(256) void attn_mma_kernel(){
    int widx  = blockIdx.x >> 1;
    int hpair = blockIdx.x & 1;

    __shared__ uint4 sQKV[6][64][4];

    int tid = threadIdx.x, lane = tid & 31, warp = tid >> 5;
    int hloc = warp >> 2, strip = warp & 3;
    int hglb = hpair*2 + hloc;

    for (int i = tid; i < 1536; i += 256){
        int hm  = i >> 8;
        int hl  = hm / 3, mat = hm % 3;
        int r   = (i >> 2) & 63;
        int c   = i & 3;
        uint4 v = make_uint4(0u,0u,0u,0u);
        if (r < 49)
            v = *reinterpret_cast<const uint4*>(
                 g_qkv + ((size_t)(widx*49 + r))*384 + mat*128 + (hpair*2 + hl)*32 + c*8);
        sQKV[hm][r][c ^ ((r >> 1) & 3)] = v;
    }
    __syncthreads();

    const uint4* Qb = &sQKV[hloc*3 + 0][0][0];
    const uint4* Kb = &sQKV[hloc*3 + 1][0][0];
    const uint4* Vb = &sQKV[hloc*3 + 2][0][0];

    auto swa = [](const uint4* base, int row, int chunk) -> uint32_t {
        return (uint32_t)__cvta_generic_to_shared(base + row*4 + (chunk ^ ((row >> 1) & 3)));
    };

    float sacc[8][4];
    #pragma unroll
    for (int i = 0; i < 8; i++){ sacc[i][0]=0.f; sacc[i][1]=0.f; sacc[i][2]=0.f; sacc[i][3]=0.f; }

    #pragma unroll
    for (int kt = 0; kt < 2; kt++){
        uint32_t aq[4];
        ldmx4(aq, swa(Qb, strip*16 + (lane & 15), kt*2 + (lane >> 4)));
        #pragma unroll
        for (int p = 0; p < 4; p++){
            uint32_t kb[4];
            ldmx4(kb, swa(Kb, p*16 + (lane & 15), kt*2 + (lane >> 4)));
            mma_bf16(sacc[2*p],   aq, kb[0], kb[2]);
            mma_bf16(sacc[2*p+1], aq, kb[1], kb[3]);
        }
    }

    const float scale = 0.17677669529663687f;
    int l4 = lane >> 2, c2 = (lane & 3)*2;
    int r0 = strip*16 + l4;
    const float* crow = g_comb + ((size_t)(widx & 255)*4 + hglb)*2401;
    bool rv[2]; int rm[2];
    #pragma unroll
    for (int i = 0; i < 2; i++){
        int r = r0 + i*8;
        rv[i] = (r < 49);
        rm[i] = r*49;
    }

    #pragma unroll
    for (int nt = 0; nt < 8; nt++){
        #pragma unroll
        for (int jc = 0; jc < 2; jc++){
            int col = nt*8 + c2 + jc;
            bool cv = (col < 49);
            #pragma unroll
            for (int i = 0; i < 2; i++){
                float v = -1e30f;
                if (cv && rv[i])
                    v = sacc[nt][i*2+jc]*scale + crow[rm[i] + col];
                sacc[nt][i*2+jc] = v;
            }
        }
    }

    float mx[2] = {-1e30f, -1e30f};
    #pragma unroll
    for (int nt = 0; nt < 8; nt++)
        #pragma unroll
        for (int j = 0; j < 4; j++) mx[j>>1] = fmaxf(mx[j>>1], sacc[nt][j]);
    #pragma unroll
    for (int i = 0; i < 2; i++){
        mx[i] = fmaxf(mx[i], __shfl_xor_sync(0xffffffffu, mx[i], 1));
        mx[i] = fmaxf(mx[i], __shfl_xor_sync(0xffffffffu, mx[i], 2));
    }
    float sum[2] = {0.f, 0.f};
    #pragma unroll
    for (int nt = 0; nt < 8; nt++)
        #pragma unroll
        for (int j = 0; j < 4; j++){
            float e = __expf(sacc[nt][j] - mx[j>>1]);
            sacc[nt][j] = e;
            sum[j>>1] += e;
        }
    #pragma unroll
    for (int i = 0; i < 2; i++){
        sum[i] += __shfl_xor_sync(0xffffffffu, sum[i], 1);
        sum[i] += __shfl_xor_sync(0xffffffffu, sum[i], 2);
    }
    float inv[2] = {1.0f/sum[0], 1.0f/sum[1]};

    float oacc[4][4];
    #pragma unroll
    for (int i = 0; i < 4; i++){ oacc[i][0]=0.f; oacc[i][1]=0.f; oacc[i][2]=0.f; oacc[i][3]=0.f; }

    #pragma unroll
    for (int kt2 = 0; kt2 < 4; kt2++){
        uint32_t pa[4];
        pa[0] = packbf(sacc[2*kt2][0],   sacc[2*kt2][1]);
        pa[1] = packbf(sacc[2*kt2][2],   sacc[2*kt2][3]);
        pa[2] = packbf(sacc[2*kt2+1][0], sacc[2*kt2+1][1]);
        pa[3] = packbf(sacc[2*kt2+1][2], sacc[2*kt2+1][3]);
        #pragma unroll
        for (int half = 0; half < 2; half++){
            uint32_t vb[4];
            ldmx4t(vb, swa(Vb, kt2*16 + (lane & 15), half*2 + (lane >> 4)));
            mma_bf16(oacc[2*half],   pa, vb[0], vb[1]);
            mma_bf16(oacc[2*half+1], pa, vb[2], vb[3]);
        }
    }

    #pragma unroll
    for (int i = 0; i < 2; i++){
        int row = r0 + i*8;
        if (row < 49){
            size_t ro = ((size_t)(widx*49 + row))*CCH + hglb*HD;
            #pragma unroll
            for (int nt = 0; nt < 4; nt++){
                __nv_bfloat162 t = __floats2bfloat162_rn(oacc[nt][i*2]*inv[i],
                                                         oacc[nt][i*2+1]*inv[i]);
                *reinterpret_cast<__nv_bfloat162*>(g_o + ro + nt*8 + c2) = t;
            }
        }
    }
}

extern __shared__ __align__(16) char smem_raw[];

// ---------------- kernel: 128x64-tile GEMM (qkv / fc1 / fc2), higher occupancy ----------------
// 8 warps: wm = warp>>1 (32-row strips), wn = warp&1 (32-col strips). acc 32 regs.
// EPI 0: QKV -> bf16 g_qkv ; EPI 1: FC1 -> gelu -> g_f1 ; EPI 3: FC2 -> +g_x1 -> out
template<int EPI>
__launch_bounds__(256, 3)
__global__ void gemm64_kernel(const float* __restrict__ bias, float* __restrict__ outf){
    constexpr int KK     = (EPI == 3) ? 512 : 128;
    constexpr int STAGES = (EPI == 3) ? 3 : 1;
    constexpr int KC     = (EPI == 3) ? 64 : 128;
    constexpr int U      = KC/8;
    constexpr int NC     = KK/KC;
    constexpr int LDO    = (EPI == 0) ? 384 : (EPI == 1) ? 512 : 128;
    const __nv_bfloat16* A = (EPI == 0) ? g_xw : (EPI == 1) ? g_ln2 : g_f1;
    const __nv_bfloat16* W = (EPI == 0) ? g_wqkv : (EPI == 1) ? g_wfc1 : g_wfc2;
    __nv_bfloat16* outb = (EPI == 0) ? g_qkv : g_f1;

    uint4* sbase = reinterpret_cast<uint4*>(smem_raw);
    uint4* sA[STAGES];
    uint4* sB[STAGES];
    #pragma unroll
    for (int s = 0; s < STAGES; s++){
        sA[s] = sbase + s*(128*U + 64*U);
        sB[s] = sA[s] + 128*U;
    }

    int tid = threadIdx.x, lane = tid & 31, warp = tid >> 5;
    int wm = warp >> 1, wn = warp & 1;
    int bm = blockIdx.x*128, bn = blockIdx.y*64;

    float acc[2][4][4];
    #pragma unroll
    for (int i = 0; i < 2; i++)
        #pragma unroll
        for (int j = 0; j < 4; j++)
            #pragma unroll
            for (int k = 0; k < 4; k++) acc[i][j][k] = 0.f;

    const __nv_bfloat16* Ag = A + (size_t)bm*KK;
    const __nv_bfloat16* Wg = W + (size_t)bn*KK;

    auto stage = [&](int c, int s){
        int kk = c*KC;
        #pragma unroll
        for (int j = 0; j < (128*U)/256; j++){
            int idx = tid + 256*j;
            int r = idx / U, u = idx - r*U;
            cp16(sA[s] + r*U + (u ^ (r & 7)), Ag + (size_t)r*KK + kk + u*8);
        }
        #pragma unroll
        for (int j = 0; j < (64*U)/256; j++){
            int idx = tid + 256*j;
            int r = idx / U, u = idx - r*U;
            cp16(sB[s] + r*U + (u ^ (r & 7)), Wg + (size_t)r*KK + kk + u*8);
        }
    };
    auto sw = [](const uint4* base, int row, int unit) -> uint32_t {
        return (uint32_t)__cvta_generic_to_shared(base + row*U + (unit ^ (row & 7)));
    };

    int arow = (lane & 15), aun = (lane >> 4);
    int brow = (lane & 7) + ((lane >> 4) << 3);
    int bun  = (lane >> 3) & 1;

    auto mma_step = [&](const uint4* sa, const uint4* sb, int ks){
        uint32_t bfr[2][4];
        ldmx4(bfr[0], sw(sb, wn*32 + brow,      ks*2 + bun));
        ldmx4(bfr[1], sw(sb, wn*32 + brow + 16, ks*2 + bun));
        #pragma unroll
        for (int mt = 0; mt < 2; mt++){
            uint32_t af[4];
            ldmx4(af, sw(sa, wm*32 + mt*16 + arow, ks*2 + aun));
            mma_bf16(acc[mt][0], af, bfr[0][0], bfr[0][1]);
            mma_bf16(acc[mt][1], af, bfr[0][2], bfr[0][3]);
            mma_bf16(acc[mt][2], af, bfr[1][0], bfr[1][1]);
            mma_bf16(acc[mt][3], af, bfr[1][2], bfr[1][3]);
        }
    };

    if constexpr (STAGES == 1){
        stage(0, 0);
        asm volatile("cp.async.commit_group;");
        asm volatile("cp.async.wait_group 0;");
        __syncthreads();
        #pragma unroll
        for (int ks = 0; ks < 8; ks++) mma_step(sA[0], sB[0], ks);
    } else {
        stage(0, 0);
        asm volatile("cp.async.commit_group;");
        stage(1, 1);
        asm volatile("cp.async.commit_group;");
        #pragma unroll
        for (int it = 0; it < NC; it++){
            if (it + 2 < NC){
                stage(it + 2, (it + 2) % 3);
                asm volatile("cp.async.commit_group;");
                asm volatile("cp.async.wait_group 2;");
            } else if (it + 1 < NC){
                asm volatile("cp.async.wait_group 1;");
            } else {
                asm volatile("cp.async.wait_group 0;");
            }
            __syncthreads();
            int s = it % 3;
            #pragma unroll
            for (int ks = 0; ks < KC/16; ks++) mma_step(sA[s], sB[s], ks);
            __syncthreads();
        }
    }

    int l4 = lane >> 2, c2 = (lane & 3)*2;
    #pragma unroll
    for (int mt = 0; mt < 2; mt++){
        int gmb = bm + wm*32 + mt*16 + l4;
        #pragma unroll
        for (int nt = 0; nt < 4; nt++){
            int gn = bn + wn*32 + nt*8 + c2;
            float bv0 = bias[gn], bv1 = bias[gn+1];
            #pragma unroll
            for (int half = 0; half < 2; half++){
                int gm = gmb + half*8;
                float v0 = acc[mt][nt][half*2+0] + bv0;
                float v1 = acc[mt][nt][half*2+1] + bv1;
                if constexpr (EPI == 0){
                    *reinterpret_cast<__nv_bfloat162*>(outb + (size_t)gm*LDO + gn) =
                        __floats2bfloat162_rn(v0, v1);
                } else if constexpr (EPI == 1){
                    *reinterpret_cast<__nv_bfloat162*>(outb + (size_t)gm*LDO + gn) =
                        __floats2bfloat162_rn(gelu_exact(v0), gelu_exact(v1));
                } else {
                    size_t o = (size_t)gm*CCH + gn;
                    float2 xr = *reinterpret_cast<const float2*>(g_x1 + o);
                    float2 t; t.x = xr.x + v0; t.y = xr.y + v1;
                    *reinterpret_cast<float2*>(outf + o) = t;
                }
            }
        }
    }
}

// ---------------- kernel: proj GEMM 128x128 + scatter + residual + fused LN2 ----------------
__launch_bounds__(256)
__global__ void proj_kernel(const float* __restrict__ bias,
                            const float* __restrict__ resid,
                            const float* __restrict__ g2,
                            const float* __restrict__ b2){
    uint4* sA = reinterpret_cast<uint4*>(smem_raw);
    uint4* sB = sA + 2048;

    int tid = threadIdx.x, lane = tid & 31, warp = tid >> 5;
    int wm = warp >> 2, wn = warp & 3;
    int bm = blockIdx.x*128;

    float acc[4][4][4];
    #pragma unroll
    for (int i = 0; i < 4; i++)
        #pragma unroll
        for (int j = 0; j < 4; j++)
            #pragma unroll
            for (int k = 0; k < 4; k++) acc[i][j][k] = 0.f;

    const __nv_bfloat16* Ag = g_o + (size_t)bm*128;

    #pragma unroll
    for (int j = 0; j < 8; j++){
        int idx = tid + 256*j;
        int r = idx >> 4, u = idx & 15;
        int ph = r*16 + (u ^ (r & 7));
        cp16(sA + ph, Ag + (size_t)r*128 + u*8);
        cp16(sB + ph, g_wproj + (size_t)r*128 + u*8);
    }
    asm volatile("cp.async.commit_group;");
    asm volatile("cp.async.wait_group 0;");
    __syncthreads();

    auto sw = [](const uint4* base, int row, int unit) -> uint32_t {
        return (uint32_t)__cvta_generic_to_shared(base + row*16 + (unit ^ (row & 7)));
    };
    int arow = (lane & 15), aun = (lane >> 4);
    int brow = (lane & 7) + ((lane >> 4) << 3);
    int bun  = (lane >> 3) & 1;

    #pragma unroll
    for (int ks = 0; ks < 8; ks++){
        uint32_t bfr[2][4];
        ldmx4(bfr[0], sw(sB, wn*32 + brow,      ks*2 + bun));
        ldmx4(bfr[1], sw(sB, wn*32 + brow + 16, ks*2 + bun));
        #pragma unroll
        for (int mt = 0; mt < 4; mt++){
            uint32_t af[4];
            ldmx4(af, sw(sA, wm*64 + mt*16 + arow, ks*2 + aun));
            mma_bf16(acc[mt][0], af, bfr[0][0], bfr[0][1]);
            mma_bf16(acc[mt][1], af, bfr[0][2], bfr[0][3]);
            mma_bf16(acc[mt][2], af, bfr[1][0], bfr[1][1]);
            mma_bf16(acc[mt][3], af, bfr[1][2], bfr[1][3]);
        }
    }

    int l4 = lane >> 2, c2 = (lane & 3)*2;
    __syncthreads();
    float* sred = reinterpret_cast<float*>(smem_raw);
    #pragma unroll
    for (int mt = 0; mt < 4; mt++){
        #pragma unroll
        for (int half = 0; half < 2; half++){
            int rloc = wm*64 + mt*16 + l4 + half*8;
            int gm = bm + rloc;
            int p = tok_map(gm);
            float s = 0.f, q = 0.f;
            #pragma unroll
            for (int nt = 0; nt < 4; nt++){
                int gn = wn*32 + nt*8 + c2;
                float2 xr = *reinterpret_cast<const float2*>(resid + (size_t)p*CCH + gn);
                float v0 = acc[mt][nt][half*2+0] + bias[gn]   + xr.x;
                float v1 = acc[mt][nt][half*2+1] + bias[gn+1] + xr.y;
                acc[mt][nt][half*2+0] = v0;
                acc[mt][nt][half*2+1] = v1;
                float2 t; t.x = v0; t.y = v1;
                *reinterpret_cast<float2*>(g_x1 + (size_t)p*CCH + gn) = t;
                s += v0 + v1; q += v0*v0 + v1*v1;
            }
            s += __shfl_xor_sync(0xffffffffu, s, 1);
            s += __shfl_xor_sync(0xffffffffu, s, 2);
            q += __shfl_xor_sync(0xffffffffu, q, 1);
            q += __shfl_xor_sync(0xffffffffu, q, 2);
            if ((lane & 3) == 0){
                sred[rloc*8 + wn]     = s;
                sred[rloc*8 + 4 + wn] = q;
            }
        }
    }
    __syncthreads();
    #pragma unroll
    for (int mt = 0; mt < 4; mt++){
        #pragma unroll
        for (int half = 0; half < 2; half++){
            int rloc = wm*64 + mt*16 + l4 + half*8;
            int gm = bm + rloc;
            int p = tok_map(gm);
            float s = sred[rloc*8+0] + sred[rloc*8+1] + sred[rloc*8+2] + sred[rloc*8+3];
            float q = sred[rloc*8+4] + sred[rloc*8+5] + sred[rloc*8+6] + sred[rloc*8+7];
            float mean = s * (1.0f/CCH);
            float var  = q * (1.0f/CCH) - mean*mean;
            float inv  = rsqrtf(var + 1e-5f);
            #pragma unroll
            for (int nt = 0; nt < 4; nt++){
                int gn = wn*32 + nt*8 + c2;
                float v0 = (acc[mt][nt][half*2+0] - mean)*inv*g2[gn]   + b2[gn];
                float v1 = (acc[mt][nt][half*2+1] - mean)*inv*g2[gn+1] + b2[gn+1];
                *reinterpret_cast<__nv_bfloat162*>(g_ln2 + (size_t)p*CCH + gn) =
                    __floats2bfloat162_rn(v0, v1);
            }
        }
    }
}

#define G64_SMEM   49152   // 1 stage: A 32KB + B 16KB
#define FC2_SMEM   73728   // 3 stages x (A 16KB + B 8KB)
#define PROJ_SMEM  65536

// ---------------- host launch ----------------
extern "C" void kernel_launch(void* const* d_in, const int* in_sizes, int n_in,
                              void* d_out, int out_size){
    int off = (n_in >= 17) ? 2 : 0;
    const float* x     = (const float*)d_in[0];
    const float* mask  = (const float*)d_in[1 + off];
    const float* ln1g  = (const float*)d_in[2 + off];
    const float* ln1b  = (const float*)d_in[3 + off];
    const float* qkvw  = (const float*)d_in[4 + off];
    const float* qkvb  = (const float*)d_in[5 + off];
    const float* relt  = (const float*)d_in[6 + off];
    const float* projw = (const float*)d_in[7 + off];
    const float* projb = (const float*)d_in[8 + off];
    const float* ln2g  = (const float*)d_in[9 + off];
    const float* ln2b  = (const float*)d_in[10 + off];
    const float* fc1w  = (const float*)d_in[11 + off];
    const float* fc1b  = (const float*)d_in[12 + off];
    const float* fc2w  = (const float*)d_in[13 + off];
    const float* fc2b  = (const float*)d_in[14 + off];
    float* out = (float*)d_out;

    cudaFuncSetAttribute(gemm64_kernel<0>, cudaFuncAttributeMaxDynamicSharedMemorySize, G64_SMEM);
    cudaFuncSetAttribute(gemm64_kernel<1>, cudaFuncAttributeMaxDynamicSharedMemorySize, G64_SMEM);
    cudaFuncSetAttribute(gemm64_kernel<3>, cudaFuncAttributeMaxDynamicSharedMemorySize, FC2_SMEM);
    cudaFuncSetAttribute(proj_kernel,      cudaFuncAttributeMaxDynamicSharedMemorySize, PROJ_SMEM);

    cvt_weights<<<256, 256>>>(qkvw, projw, fc1w, fc2w);
    comb_kernel<<<(NWIMG*NHEAD*2401 + 255)/256, 256>>>(mask, relt);
    ln1_kernel<<<MTOK/8, 256>>>(x, ln1g, ln1b);
    gemm64_kernel<0><<<dim3(MTOK/128, 6), 256, G64_SMEM>>>(qkvb, nullptr);
    attn_mma_kernel<<<BWIN*2, 256>>>();
    proj_kernel<<<MTOK/128, 256, PROJ_SMEM>>>(projb, x, ln2g, ln2b);
    gemm64_kernel<1><<<dim3(MTOK/128, 8), 256, G64_SMEM>>>(fc1b, nullptr);
    gemm64_kernel<3><<<dim3(MTOK/128, 2), 256, FC2_SMEM>>>(fc2b, out);
}

// round 16
// speedup vs baseline: 1.2919x; 1.0207x over previous
#include <cuda_runtime.h>
#include <cuda_bf16.h>
#include <cstdint>

// ---------------- problem constants ----------------
#define BATCH   16
#define HDIM    112
#define CCH     128
#define LTOK    (HDIM*HDIM)          // 12544
#define MTOK    (BATCH*LTOK)         // 200704
#define NHEAD   4
#define HD      32
#define NWIMG   256
#define BWIN    (BATCH*NWIMG)        // 4096
#define HIDDEN  512

// ---------------- scratch (device globals; no runtime alloc) ----------------
__device__ __align__(256) __nv_bfloat16 g_xw [(size_t)MTOK*CCH];
__device__ __align__(256) __nv_bfloat16 g_qkv[(size_t)MTOK*3*CCH];
__device__ __align__(256) __nv_bfloat16 g_o  [(size_t)MTOK*CCH];
__device__ __align__(256) float         g_x1 [(size_t)MTOK*CCH];
__device__ __align__(256) __nv_bfloat16 g_ln2[(size_t)MTOK*CCH];
__device__ __align__(256) __nv_bfloat16 g_f1 [(size_t)MTOK*HIDDEN];
__device__ __align__(256) __nv_bfloat16 g_wqkv[3*CCH*CCH];
__device__ __align__(256) __nv_bfloat16 g_wproj[CCH*CCH];
__device__ __align__(256) __nv_bfloat16 g_wfc1[HIDDEN*CCH];
__device__ __align__(256) __nv_bfloat16 g_wfc2[CCH*HIDDEN];
__device__ __align__(256) float g_comb[(size_t)NWIMG*NHEAD*2401];

// ---------------- helpers ----------------
__device__ __forceinline__ int tok_map(int r){
    int widx = r / 49, n = r - widx*49;
    int b  = widx >> 8, w = widx & 255;
    int wi = w >> 4,   wj = w & 15;
    int ti = n / 7,    tj = n - ti*7;
    int i = wi*7 + ti + 3; if (i >= HDIM) i -= HDIM;
    int j = wj*7 + tj + 3; if (j >= HDIM) j -= HDIM;
    return (b*HDIM + i)*HDIM + j;
}
__device__ __forceinline__ float gelu_exact(float v){
    return 0.5f * v * (1.0f + erff(v * 0.70710678118654752f));
}
__device__ __forceinline__ void ldmx4(uint32_t r[4], uint32_t a){
    asm volatile("ldmatrix.sync.aligned.m8n8.x4.shared.b16 {%0,%1,%2,%3}, [%4];"
                 : "=r"(r[0]), "=r"(r[1]), "=r"(r[2]), "=r"(r[3]) : "r"(a));
}
__device__ __forceinline__ void ldmx4t(uint32_t r[4], uint32_t a){
    asm volatile("ldmatrix.sync.aligned.m8n8.x4.trans.shared.b16 {%0,%1,%2,%3}, [%4];"
                 : "=r"(r[0]), "=r"(r[1]), "=r"(r[2]), "=r"(r[3]) : "r"(a));
}
__device__ __forceinline__ void mma_bf16(float* c, const uint32_t a[4], uint32_t b0, uint32_t b1){
    asm volatile("mma.sync.aligned.m16n8k16.row.col.f32.bf16.bf16.f32 "
                 "{%0,%1,%2,%3}, {%4,%5,%6,%7}, {%8,%9}, {%0,%1,%2,%3};"
                 : "+f"(c[0]), "+f"(c[1]), "+f"(c[2]), "+f"(c[3])
                 : "r"(a[0]), "r"(a[1]), "r"(a[2]), "r"(a[3]), "r"(b0), "r"(b1));
}
__device__ __forceinline__ void cp16(void* dst, const void* src){
    uint32_t d = (uint32_t)__cvta_generic_to_shared(dst);
    asm volatile("cp.async.cg.shared.global [%0], [%1], 16;" :: "r"(d), "l"(src));
}
__device__ __forceinline__ uint32_t packbf(float x, float y){
    __nv_bfloat162 t = __floats2bfloat162_rn(x, y);
    return *reinterpret_cast<uint32_t*>(&t);
}

// ---------------- kernel: weight conversion fp32 -> bf16 ----------------
__global__ void cvt_weights(const float* __restrict__ qkvw, const float* __restrict__ projw,
                            const float* __restrict__ fc1w, const float* __restrict__ fc2w){
    int i = blockIdx.x*blockDim.x + threadIdx.x;
    if (i < 3*CCH*CCH)  g_wqkv[i]  = __float2bfloat16(qkvw[i]);
    if (i < CCH*CCH)    g_wproj[i] = __float2bfloat16(projw[i]);
    if (i < HIDDEN*CCH){ g_wfc1[i] = __float2bfloat16(fc1w[i]);
                         g_wfc2[i] = __float2bfloat16(fc2w[i]); }
}

// ---------------- kernel: combined mask + rel-pos bias table ----------------
__global__ void comb_kernel(const float* __restrict__ mask, const float* __restrict__ table){
    int idx = blockIdx.x*256 + threadIdx.x;
    if (idx >= NWIMG*NHEAD*2401) return;
    int nm = idx % 2401, wh = idx / 2401;
    int h = wh & 3, w = wh >> 2;
    int n = nm / 49, m = nm - n*49;
    int ni = n/7, nj = n - ni*7, mi = m/7, mj = m - mi*7;
    g_comb[idx] = mask[w*2401 + nm] + table[((ni-mi+6)*13 + (nj-mj+6))*4 + h];
}

// ---------------- kernel: LayerNorm1, warp-per-row, gather permutation ----------------
__global__ __launch_bounds__(256) void ln1_kernel(const float* __restrict__ xin,
                                                  const float* __restrict__ g,
                                                  const float* __restrict__ b){
    int lane = threadIdx.x & 31, warp = threadIdx.x >> 5;
    int r = blockIdx.x*8 + warp;
    int p = tok_map(r);
    float4 v = *reinterpret_cast<const float4*>(xin + (size_t)p*CCH + lane*4);
    float s = v.x + v.y + v.z + v.w;
    float q = v.x*v.x + v.y*v.y + v.z*v.z + v.w*v.w;
    #pragma unroll
    for (int o = 16; o > 0; o >>= 1){
        s += __shfl_xor_sync(0xffffffffu, s, o);
        q += __shfl_xor_sync(0xffffffffu, q, o);
    }
    float mean = s * (1.0f/CCH);
    float inv  = rsqrtf(q * (1.0f/CCH) - mean*mean + 1e-5f);
    float4 gg = *reinterpret_cast<const float4*>(g + lane*4);
    float4 bb = *reinterpret_cast<const float4*>(b + lane*4);
    __nv_bfloat162 o0 = __floats2bfloat162_rn((v.x-mean)*inv*gg.x + bb.x,
                                              (v.y-mean)*inv*gg.y + bb.y);
    __nv_bfloat162 o1 = __floats2bfloat162_rn((v.z-mean)*inv*gg.z + bb.z,
                                              (v.w-mean)*inv*gg.w + bb.w);
    uint2 st; st.x = *reinterpret_cast<uint32_t*>(&o0); st.y = *reinterpret_cast<uint32_t*>(&o1);
    *reinterpret_cast<uint2*>(g_xw + (size_t)r*CCH + lane*4) = st;
}

// ---------------- kernel: tensor-core windowed attention ----------------
__global__ __launch_bounds__(256) void attn_mma_kernel(){
    int widx  = blockIdx.x >> 1;
    int hpair = blockIdx.x & 1;

    __shared__ uint4 sQKV[6][64][4];

    int tid = threadIdx.x, lane = tid & 31, warp = tid >> 5;
    int hloc = warp >> 2, strip = warp & 3;
    int hglb = hpair*2 + hloc;

    for (int i = tid; i < 1536; i += 256){
        int hm  = i >> 8;
        int hl  = hm / 3, mat = hm % 3;
        int r   = (i >> 2) & 63;
        int c   = i & 3;
        uint4 v = make_uint4(0u,0u,0u,0u);
        if (r < 49)
            v = *reinterpret_cast<const uint4*>(
                 g_qkv + ((size_t)(widx*49 + r))*384 + mat*128 + (hpair*2 + hl)*32 + c*8);
        sQKV[hm][r][c ^ ((r >> 1) & 3)] = v;
    }
    __syncthreads();

    const uint4* Qb = &sQKV[hloc*3 + 0][0][0];
    const uint4* Kb = &sQKV[hloc*3 + 1][0][0];
    const uint4* Vb = &sQKV[hloc*3 + 2][0][0];

    auto swa = [](const uint4* base, int row, int chunk) -> uint32_t {
        return (uint32_t)__cvta_generic_to_shared(base + row*4 + (chunk ^ ((row >> 1) & 3)));
    };

    float sacc[8][4];
    #pragma unroll
    for (int i = 0; i < 8; i++){ sacc[i][0]=0.f; sacc[i][1]=0.f; sacc[i][2]=0.f; sacc[i][3]=0.f; }

    #pragma unroll
    for (int kt = 0; kt < 2; kt++){
        uint32_t aq[4];
        ldmx4(aq, swa(Qb, strip*16 + (lane & 15), kt*2 + (lane >> 4)));
        #pragma unroll
        for (int p = 0; p < 4; p++){
            uint32_t kb[4];
            ldmx4(kb, swa(Kb, p*16 + (lane & 15), kt*2 + (lane >> 4)));
            mma_bf16(sacc[2*p],   aq, kb[0], kb[2]);
            mma_bf16(sacc[2*p+1], aq, kb[1], kb[3]);
        }
    }

    const float scale = 0.17677669529663687f;
    int l4 = lane >> 2, c2 = (lane & 3)*2;
    int r0 = strip*16 + l4;
    const float* crow = g_comb + ((size_t)(widx & 255)*4 + hglb)*2401;
    bool rv[2]; int rm[2];
    #pragma unroll
    for (int i = 0; i < 2; i++){
        int r = r0 + i*8;
        rv[i] = (r < 49);
        rm[i] = r*49;
    }

    #pragma unroll
    for (int nt = 0; nt < 8; nt++){
        #pragma unroll
        for (int jc = 0; jc < 2; jc++){
            int col = nt*8 + c2 + jc;
            bool cv = (col < 49);
            #pragma unroll
            for (int i = 0; i < 2; i++){
                float v = -1e30f;
                if (cv && rv[i])
                    v = sacc[nt][i*2+jc]*scale + crow[rm[i] + col];
                sacc[nt][i*2+jc] = v;
            }
        }
    }

    float mx[2] = {-1e30f, -1e30f};
    #pragma unroll
    for (int nt = 0; nt < 8; nt++)
        #pragma unroll
        for (int j = 0; j < 4; j++) mx[j>>1] = fmaxf(mx[j>>1], sacc[nt][j]);
    #pragma unroll
    for (int i = 0; i < 2; i++){
        mx[i] = fmaxf(mx[i], __shfl_xor_sync(0xffffffffu, mx[i], 1));
        mx[i] = fmaxf(mx[i], __shfl_xor_sync(0xffffffffu, mx[i], 2));
    }
    float sum[2] = {0.f, 0.f};
    #pragma unroll
    for (int nt = 0; nt < 8; nt++)
        #pragma unroll
        for (int j = 0; j < 4; j++){
            float e = __expf(sacc[nt][j] - mx[j>>1]);
            sacc[nt][j] = e;
            sum[j>>1] += e;
        }
    #pragma unroll
    for (int i = 0; i < 2; i++){
        sum[i] += __shfl_xor_sync(0xffffffffu, sum[i], 1);
        sum[i] += __shfl_xor_sync(0xffffffffu, sum[i], 2);
    }
    float inv[2] = {1.0f/sum[0], 1.0f/sum[1]};

    float oacc[4][4];
    #pragma unroll
    for (int i = 0; i < 4; i++){ oacc[i][0]=0.f; oacc[i][1]=0.f; oacc[i][2]=0.f; oacc[i][3]=0.f; }

    #pragma unroll
    for (int kt2 = 0; kt2 < 4; kt2++){
        uint32_t pa[4];
        pa[0] = packbf(sacc[2*kt2][0],   sacc[2*kt2][1]);
        pa[1] = packbf(sacc[2*kt2][2],   sacc[2*kt2][3]);
        pa[2] = packbf(sacc[2*kt2+1][0], sacc[2*kt2+1][1]);
        pa[3] = packbf(sacc[2*kt2+1][2], sacc[2*kt2+1][3]);
        #pragma unroll
        for (int half = 0; half < 2; half++){
            uint32_t vb[4];
            ldmx4t(vb, swa(Vb, kt2*16 + (lane & 15), half*2 + (lane >> 4)));
            mma_bf16(oacc[2*half],   pa, vb[0], vb[1]);
            mma_bf16(oacc[2*half+1], pa, vb[2], vb[3]);
        }
    }

    #pragma unroll
    for (int i = 0; i < 2; i++){
        int row = r0 + i*8;
        if (row < 49){
            size_t ro = ((size_t)(widx*49 + row))*CCH + hglb*HD;
            #pragma unroll
            for (int nt = 0; nt < 4; nt++){
                __nv_bfloat162 t = __floats2bfloat162_rn(oacc[nt][i*2]*inv[i],
                                                         oacc[nt][i*2+1]*inv[i]);
                *reinterpret_cast<__nv_bfloat162*>(g_o + ro + nt*8 + c2) = t;
            }
        }
    }
}

extern __shared__ __align__(16) char smem_raw[];

// ---------------- kernel: 128x128-tile single-stage GEMM (qkv / fc1), K=128 ----------------
// EPI 0: QKV -> bf16 g_qkv ; EPI 1: FC1 -> gelu -> bf16 g_f1
template<int EPI>
__launch_bounds__(256)
__global__ void gemm128_kernel(const float* __restrict__ bias){
    constexpr int LDO = (EPI == 0) ? 384 : 512;
    const __nv_bfloat16* A = (EPI == 0) ? g_xw  : g_ln2;
    const __nv_bfloat16* W = (EPI == 0) ? g_wqkv : g_wfc1;
    __nv_bfloat16* outb    = (EPI == 0) ? g_qkv : g_f1;

    uint4* sA = reinterpret_cast<uint4*>(smem_raw);
    uint4* sB = sA + 2048;

    int tid = threadIdx.x, lane = tid & 31, warp = tid >> 5;
    int wm = warp >> 2, wn = warp & 3;
    int bm = blockIdx.x*128, bn = blockIdx.y*128;

    float acc[4][4][4];
    #pragma unroll
    for (int i = 0; i < 4; i++)
        #pragma unroll
        for (int j = 0; j < 4; j++)
            #pragma unroll
            for (int k = 0; k < 4; k++) acc[i][j][k] = 0.f;

    const __nv_bfloat16* Ag = A + (size_t)bm*128;
    const __nv_bfloat16* Wg = W + (size_t)bn*128;

    #pragma unroll
    for (int j = 0; j < 8; j++){
        int idx = tid + 256*j;
        int r = idx >> 4, u = idx & 15;
        int ph = r*16 + (u ^ (r & 7));
        cp16(sA + ph, Ag + (size_t)r*128 + u*8);
        cp16(sB + ph, Wg + (size_t)r*128 + u*8);
    }
    asm volatile("cp.async.commit_group;");
    asm volatile("cp.async.wait_group 0;");
    __syncthreads();

    auto sw = [](const uint4* base, int row, int unit) -> uint32_t {
        return (uint32_t)__cvta_generic_to_shared(base + row*16 + (unit ^ (row & 7)));
    };
    int arow = (lane & 15), aun = (lane >> 4);
    int brow = (lane & 7) + ((lane >> 4) << 3);
    int bun  = (lane >> 3) & 1;

    #pragma unroll
    for (int ks = 0; ks < 8; ks++){
        uint32_t bfr[2][4];
        ldmx4(bfr[0], sw(sB, wn*32 + brow,      ks*2 + bun));
        ldmx4(bfr[1], sw(sB, wn*32 + brow + 16, ks*2 + bun));
        #pragma unroll
        for (int mt = 0; mt < 4; mt++){
            uint32_t af[4];
            ldmx4(af, sw(sA, wm*64 + mt*16 + arow, ks*2 + aun));
            mma_bf16(acc[mt][0], af, bfr[0][0], bfr[0][1]);
            mma_bf16(acc[mt][1], af, bfr[0][2], bfr[0][3]);
            mma_bf16(acc[mt][2], af, bfr[1][0], bfr[1][1]);
            mma_bf16(acc[mt][3], af, bfr[1][2], bfr[1][3]);
        }
    }

    int l4 = lane >> 2, c2 = (lane & 3)*2;
    #pragma unroll
    for (int mt = 0; mt < 4; mt++){
        int gmb = bm + wm*64 + mt*16 + l4;
        #pragma unroll
        for (int nt = 0; nt < 4; nt++){
            int gn = bn + wn*32 + nt*8 + c2;
            float bv0 = bias[gn], bv1 = bias[gn+1];
            #pragma unroll
            for (int half = 0; half < 2; half++){
                int gm = gmb + half*8;
                float v0 = acc[mt][nt][half*2+0] + bv0;
                float v1 = acc[mt][nt][half*2+1] + bv1;
                if constexpr (EPI == 0){
                    *reinterpret_cast<__nv_bfloat162*>(outb + (size_t)gm*LDO + gn) =
                        __floats2bfloat162_rn(v0, v1);
                } else {
                    *reinterpret_cast<__nv_bfloat162*>(outb + (size_t)gm*LDO + gn) =
                        __floats2bfloat162_rn(gelu_exact(v0), gelu_exact(v1));
                }
            }
        }
    }
}

// ---------------- kernel: proj GEMM 128x128 + scatter + residual + fused LN2 ----------------
__launch_bounds__(256)
__global__ void proj_kernel(const float* __restrict__ bias,
                            const float* __restrict__ resid,
                            const float* __restrict__ g2,
                            const float* __restrict__ b2){
    uint4* sA = reinterpret_cast<uint4*>(smem_raw);
    uint4* sB = sA + 2048;

    int tid = threadIdx.x, lane = tid & 31, warp = tid >> 5;
    int wm = warp >> 2, wn = warp & 3;
    int bm = blockIdx.x*128;

    float acc[4][4][4];
    #pragma unroll
    for (int i = 0; i < 4; i++)
        #pragma unroll
        for (int j = 0; j < 4; j++)
            #pragma unroll
            for (int k = 0; k < 4; k++) acc[i][j][k] = 0.f;

    const __nv_bfloat16* Ag = g_o + (size_t)bm*128;

    #pragma unroll
    for (int j = 0; j < 8; j++){
        int idx = tid + 256*j;
        int r = idx >> 4, u = idx & 15;
        int ph = r*16 + (u ^ (r & 7));
        cp16(sA + ph, Ag + (size_t)r*128 + u*8);
        cp16(sB + ph, g_wproj + (size_t)r*128 + u*8);
    }
    asm volatile("cp.async.commit_group;");
    asm volatile("cp.async.wait_group 0;");
    __syncthreads();

    auto sw = [](const uint4* base, int row, int unit) -> uint32_t {
        return (uint32_t)__cvta_generic_to_shared(base + row*16 + (unit ^ (row & 7)));
    };
    int arow = (lane & 15), aun = (lane >> 4);
    int brow = (lane & 7) + ((lane >> 4) << 3);
    int bun  = (lane >> 3) & 1;

    #pragma unroll
    for (int ks = 0; ks < 8; ks++){
        uint32_t bfr[2][4];
        ldmx4(bfr[0], sw(sB, wn*32 + brow,      ks*2 + bun));
        ldmx4(bfr[1], sw(sB, wn*32 + brow + 16, ks*2 + bun));
        #pragma unroll
        for (int mt = 0; mt < 4; mt++){
            uint32_t af[4];
            ldmx4(af, sw(sA, wm*64 + mt*16 + arow, ks*2 + aun));
            mma_bf16(acc[mt][0], af, bfr[0][0], bfr[0][1]);
            mma_bf16(acc[mt][1], af, bfr[0][2], bfr[0][3]);
            mma_bf16(acc[mt][2], af, bfr[1][0], bfr[1][1]);
            mma_bf16(acc[mt][3], af, bfr[1][2], bfr[1][3]);
        }
    }

    int l4 = lane >> 2, c2 = (lane & 3)*2;
    __syncthreads();
    float* sred = reinterpret_cast<float*>(smem_raw);
    #pragma unroll
    for (int mt = 0; mt < 4; mt++){
        #pragma unroll
        for (int half = 0; half < 2; half++){
            int rloc = wm*64 + mt*16 + l4 + half*8;
            int gm = bm + rloc;
            int p = tok_map(gm);
            float s = 0.f, q = 0.f;
            #pragma unroll
            for (int nt = 0; nt < 4; nt++){
                int gn = wn*32 + nt*8 + c2;
                float2 xr = *reinterpret_cast<const float2*>(resid + (size_t)p*CCH + gn);
                float v0 = acc[mt][nt][half*2+0] + bias[gn]   + xr.x;
                float v1 = acc[mt][nt][half*2+1] + bias[gn+1] + xr.y;
                acc[mt][nt][half*2+0] = v0;
                acc[mt][nt][half*2+1] = v1;
                float2 t; t.x = v0; t.y = v1;
                *reinterpret_cast<float2*>(g_x1 + (size_t)p*CCH + gn) = t;
                s += v0 + v1; q += v0*v0 + v1*v1;
            }
            s += __shfl_xor_sync(0xffffffffu, s, 1);
            s += __shfl_xor_sync(0xffffffffu, s, 2);
            q += __shfl_xor_sync(0xffffffffu, q, 1);
            q += __shfl_xor_sync(0xffffffffu, q, 2);
            if ((lane & 3) == 0){
                sred[rloc*8 + wn]     = s;
                sred[rloc*8 + 4 + wn] = q;
            }
        }
    }
    __syncthreads();
    #pragma unroll
    for (int mt = 0; mt < 4; mt++){
        #pragma unroll
        for (int half = 0; half < 2; half++){
            int rloc = wm*64 + mt*16 + l4 + half*8;
            int gm = bm + rloc;
            int p = tok_map(gm);
            float s = sred[rloc*8+0] + sred[rloc*8+1] + sred[rloc*8+2] + sred[rloc*8+3];
            float q = sred[rloc*8+4] + sred[rloc*8+5] + sred[rloc*8+6] + sred[rloc*8+7];
            float mean = s * (1.0f/CCH);
            float var  = q * (1.0f/CCH) - mean*mean;
            float inv  = rsqrtf(var + 1e-5f);
            #pragma unroll
            for (int nt = 0; nt < 4; nt++){
                int gn = wn*32 + nt*8 + c2;
                float v0 = (acc[mt][nt][half*2+0] - mean)*inv*g2[gn]   + b2[gn];
                float v1 = (acc[mt][nt][half*2+1] - mean)*inv*g2[gn+1] + b2[gn+1];
                *reinterpret_cast<__nv_bfloat162*>(g_ln2 + (size_t)p*CCH + gn) =
                    __floats2bfloat162_rn(v0, v1);
            }
        }
    }
}

// ---------------- kernel: fc2 GEMM (K=512), HMMA 128x64 3-stage (R11) ----------------
__launch_bounds__(256, 3)
__global__ void fc2_kernel(const float* __restrict__ bias, float* __restrict__ outf){
    constexpr int KK = 512, KC = 64, U = 8, NC = KK/KC;
    uint4* sbase = reinterpret_cast<uint4*>(smem_raw);
    uint4* sA[3]; uint4* sB[3];
    #pragma unroll
    for (int s = 0; s < 3; s++){
        sA[s] = sbase + s*(128*U + 64*U);
        sB[s] = sA[s] + 128*U;
    }

    int tid = threadIdx.x, lane = tid & 31, warp = tid >> 5;
    int wm = warp >> 1, wn = warp & 1;
    int bm = blockIdx.x*128, bn = blockIdx.y*64;

    float acc[2][4][4];
    #pragma unroll
    for (int i = 0; i < 2; i++)
        #pragma unroll
        for (int j = 0; j < 4; j++)
            #pragma unroll
            for (int k = 0; k < 4; k++) acc[i][j][k] = 0.f;

    const __nv_bfloat16* Ag = g_f1 + (size_t)bm*KK;
    const __nv_bfloat16* Wg = g_wfc2 + (size_t)bn*KK;

    auto stage = [&](int c, int s){
        int kk = c*KC;
        #pragma unroll
        for (int j = 0; j < (128*U)/256; j++){
            int idx = tid + 256*j;
            int r = idx / U, u = idx - r*U;
            cp16(sA[s] + r*U + (u ^ (r & 7)), Ag + (size_t)r*KK + kk + u*8);
        }
        #pragma unroll
        for (int j = 0; j < (64*U)/256; j++){
            int idx = tid + 256*j;
            int r = idx / U, u = idx - r*U;
            cp16(sB[s] + r*U + (u ^ (r & 7)), Wg + (size_t)r*KK + kk + u*8);
        }
    };
    auto sw = [](const uint4* base, int row, int unit) -> uint32_t {
        return (uint32_t)__cvta_generic_to_shared(base + row*U + (unit ^ (row & 7)));
    };

    int arow = (lane & 15), aun = (lane >> 4);
    int brow = (lane & 7) + ((lane >> 4) << 3);
    int bun  = (lane >> 3) & 1;

    auto mma_step = [&](const uint4* sa, const uint4* sb, int ks){
        uint32_t bfr[2][4];
        ldmx4(bfr[0], sw(sb, wn*32 + brow,      ks*2 + bun));
        ldmx4(bfr[1], sw(sb, wn*32 + brow + 16, ks*2 + bun));
        #pragma unroll
        for (int mt = 0; mt < 2; mt++){
            uint32_t af[4];
            ldmx4(af, sw(sa, wm*32 + mt*16 + arow, ks*2 + aun));
            mma_bf16(acc[mt][0], af, bfr[0][0], bfr[0][1]);
            mma_bf16(acc[mt][1], af, bfr[0][2], bfr[0][3]);
            mma_bf16(acc[mt][2], af, bfr[1][0], bfr[1][1]);
            mma_bf16(acc[mt][3], af, bfr[1][2], bfr[1][3]);
        }
    };

    stage(0, 0);
    asm volatile("cp.async.commit_group;");
    stage(1, 1);
    asm volatile("cp.async.commit_group;");
    #pragma unroll
    for (int it = 0; it < NC; it++){
        if (it + 2 < NC){
            stage(it + 2, (it + 2) % 3);
            asm volatile("cp.async.commit_group;");
            asm volatile("cp.async.wait_group 2;");
        } else if (it + 1 < NC){
            asm volatile("cp.async.wait_group 1;");
        } else {
            asm volatile("cp.async.wait_group 0;");
        }
        __syncthreads();
        int s = it % 3;
        #pragma unroll
        for (int ks = 0; ks < KC/16; ks++) mma_step(sA[s], sB[s], ks);
        __syncthreads();
    }

    int l4 = lane >> 2, c2 = (lane & 3)*2;
    #pragma unroll
    for (int mt = 0; mt < 2; mt++){
        int gmb = bm + wm*32 + mt*16 + l4;
        #pragma unroll
        for (int nt = 0; nt < 4; nt++){
            int gn = bn + wn*32 + nt*8 + c2;
            float bv0 = bias[gn], bv1 = bias[gn+1];
            #pragma unroll
            for (int half = 0; half < 2; half++){
                int gm = gmb + half*8;
                size_t o = (size_t)gm*CCH + gn;
                float2 xr = *reinterpret_cast<const float2*>(g_x1 + o);
                float2 t;
                t.x = xr.x + acc[mt][nt][half*2+0] + bv0;
                t.y = xr.y + acc[mt][nt][half*2+1] + bv1;
                *reinterpret_cast<float2*>(outf + o) = t;
            }
        }
    }
}

#define G128_SMEM  65536   // 1 stage: A 32KB + B 32KB
#define FC2_SMEM   73728   // 3 stages x (A 16KB + B 8KB)
#define PROJ_SMEM  65536

// ---------------- host launch ----------------
extern "C" void kernel_launch(void* const* d_in, const int* in_sizes, int n_in,
                              void* d_out, int out_size){
    int off = (n_in >= 17) ? 2 : 0;
    const float* x     = (const float*)d_in[0];
    const float* mask  = (const float*)d_in[1 + off];
    const float* ln1g  = (const float*)d_in[2 + off];
    const float* ln1b  = (const float*)d_in[3 + off];
    const float* qkvw  = (const float*)d_in[4 + off];
    const float* qkvb  = (const float*)d_in[5 + off];
    const float* relt  = (const float*)d_in[6 + off];
    const float* projw = (const float*)d_in[7 + off];
    const float* projb = (const float*)d_in[8 + off];
    const float* ln2g  = (const float*)d_in[9 + off];
    const float* ln2b  = (const float*)d_in[10 + off];
    const float* fc1w  = (const float*)d_in[11 + off];
    const float* fc1b  = (const float*)d_in[12 + off];
    const float* fc2w  = (const float*)d_in[13 + off];
    const float* fc2b  = (const float*)d_in[14 + off];
    float* out = (float*)d_out;

    cudaFuncSetAttribute(gemm128_kernel<0>, cudaFuncAttributeMaxDynamicSharedMemorySize, G128_SMEM);
    cudaFuncSetAttribute(gemm128_kernel<1>, cudaFuncAttributeMaxDynamicSharedMemorySize, G128_SMEM);
    cudaFuncSetAttribute(proj_kernel,       cudaFuncAttributeMaxDynamicSharedMemorySize, PROJ_SMEM);
    cudaFuncSetAttribute(fc2_kernel,        cudaFuncAttributeMaxDynamicSharedMemorySize, FC2_SMEM);

    cvt_weights<<<256, 256>>>(qkvw, projw, fc1w, fc2w);
    comb_kernel<<<(NWIMG*NHEAD*2401 + 255)/256, 256>>>(mask, relt);
    ln1_kernel<<<MTOK/8, 256>>>(x, ln1g, ln1b);
    gemm128_kernel<0><<<dim3(MTOK/128, 3), 256, G128_SMEM>>>(qkvb);
    attn_mma_kernel<<<BWIN*2, 256>>>();
    proj_kernel<<<MTOK/128, 256, PROJ_SMEM>>>(projb, x, ln2g, ln2b);
    gemm128_kernel<1><<<dim3(MTOK/128, 4), 256, G128_SMEM>>>(fc1b);
    fc2_kernel<<<dim3(MTOK/128, 2), 256, FC2_SMEM>>>(fc2b, out);
}

// round 17
// speedup vs baseline: 1.2941x; 1.0017x over previous
#include <cuda_runtime.h>
#include <cuda_bf16.h>
#include <cstdint>

// ---------------- problem constants ----------------
#define BATCH   16
#define HDIM    112
#define CCH     128
#define LTOK    (HDIM*HDIM)          // 12544
#define MTOK    (BATCH*LTOK)         // 200704
#define NHEAD   4
#define HD      32
#define NWIMG   256
#define BWIN    (BATCH*NWIMG)        // 4096
#define HIDDEN  512

// ---------------- scratch (device globals; no runtime alloc) ----------------
__device__ __align__(256) __nv_bfloat16 g_xw [(size_t)MTOK*CCH];
__device__ __align__(256) __nv_bfloat16 g_qkv[(size_t)MTOK*3*CCH];
__device__ __align__(256) __nv_bfloat16 g_o  [(size_t)MTOK*CCH];
__device__ __align__(256) float         g_x1 [(size_t)MTOK*CCH];
__device__ __align__(256) __nv_bfloat16 g_ln2[(size_t)MTOK*CCH];
__device__ __align__(256) __nv_bfloat16 g_f1 [(size_t)MTOK*HIDDEN];
__device__ __align__(256) __nv_bfloat16 g_wqkv[3*CCH*CCH];
__device__ __align__(256) __nv_bfloat16 g_wproj[CCH*CCH];
__device__ __align__(256) __nv_bfloat16 g_wfc1[HIDDEN*CCH];
__device__ __align__(256) __nv_bfloat16 g_wfc2[CCH*HIDDEN];
__device__ __align__(256) __nv_bfloat16 g_comb64[(size_t)NWIMG*NHEAD*64*64]; // padded bf16

// ---------------- helpers ----------------
__device__ __forceinline__ int tok_map(int r){
    int widx = r / 49, n = r - widx*49;
    int b  = widx >> 8, w = widx & 255;
    int wi = w >> 4,   wj = w & 15;
    int ti = n / 7,    tj = n - ti*7;
    int i = wi*7 + ti + 3; if (i >= HDIM) i -= HDIM;
    int j = wj*7 + tj + 3; if (j >= HDIM) j -= HDIM;
    return (b*HDIM + i)*HDIM + j;
}
__device__ __forceinline__ float gelu_exact(float v){
    return 0.5f * v * (1.0f + erff(v * 0.70710678118654752f));
}
__device__ __forceinline__ void ldmx4(uint32_t r[4], uint32_t a){
    asm volatile("ldmatrix.sync.aligned.m8n8.x4.shared.b16 {%0,%1,%2,%3}, [%4];"
                 : "=r"(r[0]), "=r"(r[1]), "=r"(r[2]), "=r"(r[3]) : "r"(a));
}
__device__ __forceinline__ void ldmx4t(uint32_t r[4], uint32_t a){
    asm volatile("ldmatrix.sync.aligned.m8n8.x4.trans.shared.b16 {%0,%1,%2,%3}, [%4];"
                 : "=r"(r[0]), "=r"(r[1]), "=r"(r[2]), "=r"(r[3]) : "r"(a));
}
__device__ __forceinline__ void mma_bf16(float* c, const uint32_t a[4], uint32_t b0, uint32_t b1){
    asm volatile("mma.sync.aligned.m16n8k16.row.col.f32.bf16.bf16.f32 "
                 "{%0,%1,%2,%3}, {%4,%5,%6,%7}, {%8,%9}, {%0,%1,%2,%3};"
                 : "+f"(c[0]), "+f"(c[1]), "+f"(c[2]), "+f"(c[3])
                 : "r"(a[0]), "r"(a[1]), "r"(a[2]), "r"(a[3]), "r"(b0), "r"(b1));
}
__device__ __forceinline__ void cp16(void* dst, const void* src){
    uint32_t d = (uint32_t)__cvta_generic_to_shared(dst);
    asm volatile("cp.async.cg.shared.global [%0], [%1], 16;" :: "r"(d), "l"(src));
}
__device__ __forceinline__ uint32_t packbf(float x, float y){
    __nv_bfloat162 t = __floats2bfloat162_rn(x, y);
    return *reinterpret_cast<uint32_t*>(&t);
}

// ---------------- kernel: weight conversion fp32 -> bf16 ----------------
__global__ void cvt_weights(const float* __restrict__ qkvw, const float* __restrict__ projw,
                            const float* __restrict__ fc1w, const float* __restrict__ fc2w){
    int i = blockIdx.x*blockDim.x + threadIdx.x;
    if (i < 3*CCH*CCH)  g_wqkv[i]  = __float2bfloat16(qkvw[i]);
    if (i < CCH*CCH)    g_wproj[i] = __float2bfloat16(projw[i]);
    if (i < HIDDEN*CCH){ g_wfc1[i] = __float2bfloat16(fc1w[i]);
                         g_wfc2[i] = __float2bfloat16(fc2w[i]); }
}

// ---------------- kernel: padded bf16 mask+bias table [256][4][64][64] ----------------
__global__ void comb_kernel(const float* __restrict__ mask, const float* __restrict__ table){
    int idx = blockIdx.x*256 + threadIdx.x;
    if (idx >= NWIMG*NHEAD*64*64) return;
    int pos = idx & 4095, wh = idx >> 12;
    int h = wh & 3, w = wh >> 2;
    int row = pos >> 6, col = pos & 63;
    float v;
    if (col >= 49)      v = -30000.f;
    else if (row >= 49) v = 0.f;
    else {
        int ni = row/7, nj = row - ni*7, mi = col/7, mj = col - mi*7;
        v = mask[w*2401 + row*49 + col] + table[((ni-mi+6)*13 + (nj-mj+6))*4 + h];
    }
    g_comb64[idx] = __float2bfloat16(v);
}

// ---------------- kernel: LayerNorm1, warp-per-row, gather permutation ----------------
__global__ __launch_bounds__(256) void ln1_kernel(const float* __restrict__ xin,
                                                  const float* __restrict__ g,
                                                  const float* __restrict__ b){
    int lane = threadIdx.x & 31, warp = threadIdx.x >> 5;
    int r = blockIdx.x*8 + warp;
    int p = tok_map(r);
    float4 v = *reinterpret_cast<const float4*>(xin + (size_t)p*CCH + lane*4);
    float s = v.x + v.y + v.z + v.w;
    float q = v.x*v.x + v.y*v.y + v.z*v.z + v.w*v.w;
    #pragma unroll
    for (int o = 16; o > 0; o >>= 1){
        s += __shfl_xor_sync(0xffffffffu, s, o);
        q += __shfl_xor_sync(0xffffffffu, q, o);
    }
    float mean = s * (1.0f/CCH);
    float inv  = rsqrtf(q * (1.0f/CCH) - mean*mean + 1e-5f);
    float4 gg = *reinterpret_cast<const float4*>(g + lane*4);
    float4 bb = *reinterpret_cast<const float4*>(b + lane*4);
    __nv_bfloat162 o0 = __floats2bfloat162_rn((v.x-mean)*inv*gg.x + bb.x,
                                              (v.y-mean)*inv*gg.y + bb.y);
    __nv_bfloat162 o1 = __floats2bfloat162_rn((v.z-mean)*inv*gg.z + bb.z,
                                              (v.w-mean)*inv*gg.w + bb.w);
    uint2 st; st.x = *reinterpret_cast<uint32_t*>(&o0); st.y = *reinterpret_cast<uint32_t*>(&o1);
    *reinterpret_cast<uint2*>(g_xw + (size_t)r*CCH + lane*4) = st;
}

// ---------------- kernel: tensor-core windowed attention (padded bf16 comb) ----------------
__global__ __launch_bounds__(256) void attn_mma_kernel(){
    int widx  = blockIdx.x >> 1;
    int hpair = blockIdx.x & 1;

    __shared__ uint4 sQKV[6][64][4];

    int tid = threadIdx.x, lane = tid & 31, warp = tid >> 5;
    int hloc = warp >> 2, strip = warp & 3;
    int hglb = hpair*2 + hloc;

    for (int i = tid; i < 1536; i += 256){
        int hm  = i >> 8;
        int hl  = hm / 3, mat = hm % 3;
        int r   = (i >> 2) & 63;
        int c   = i & 3;
        uint4 v = make_uint4(0u,0u,0u,0u);
        if (r < 49)
            v = *reinterpret_cast<const uint4*>(
                 g_qkv + ((size_t)(widx*49 + r))*384 + mat*128 + (hpair*2 + hl)*32 + c*8);
        sQKV[hm][r][c ^ ((r >> 1) & 3)] = v;
    }
    __syncthreads();

    const uint4* Qb = &sQKV[hloc*3 + 0][0][0];
    const uint4* Kb = &sQKV[hloc*3 + 1][0][0];
    const uint4* Vb = &sQKV[hloc*3 + 2][0][0];

    auto swa = [](const uint4* base, int row, int chunk) -> uint32_t {
        return (uint32_t)__cvta_generic_to_shared(base + row*4 + (chunk ^ ((row >> 1) & 3)));
    };

    float sacc[8][4];
    #pragma unroll
    for (int i = 0; i < 8; i++){ sacc[i][0]=0.f; sacc[i][1]=0.f; sacc[i][2]=0.f; sacc[i][3]=0.f; }

    #pragma unroll
    for (int kt = 0; kt < 2; kt++){
        uint32_t aq[4];
        ldmx4(aq, swa(Qb, strip*16 + (lane & 15), kt*2 + (lane >> 4)));
        #pragma unroll
        for (int p = 0; p < 4; p++){
            uint32_t kb[4];
            ldmx4(kb, swa(Kb, p*16 + (lane & 15), kt*2 + (lane >> 4)));
            mma_bf16(sacc[2*p],   aq, kb[0], kb[2]);
            mma_bf16(sacc[2*p+1], aq, kb[1], kb[3]);
        }
    }

    // ---- scale + padded combined bias/mask (bf16x2 loads, branch-free) ----
    const float scale = 0.17677669529663687f;
    int l4 = lane >> 2, c2 = (lane & 3)*2;
    int r0 = strip*16 + l4;
    const __nv_bfloat16* crow = g_comb64 + ((size_t)((widx & 255)*4 + hglb) << 12);

    #pragma unroll
    for (int nt = 0; nt < 8; nt++){
        #pragma unroll
        for (int i = 0; i < 2; i++){
            uint32_t cw = *reinterpret_cast<const uint32_t*>(crow + ((r0 + i*8) << 6) + nt*8 + c2);
            float2 cb = __bfloat1622float2(*reinterpret_cast<__nv_bfloat162*>(&cw));
            sacc[nt][i*2+0] = sacc[nt][i*2+0]*scale + cb.x;
            sacc[nt][i*2+1] = sacc[nt][i*2+1]*scale + cb.y;
        }
    }

    float mx[2] = {-1e30f, -1e30f};
    #pragma unroll
    for (int nt = 0; nt < 8; nt++)
        #pragma unroll
        for (int j = 0; j < 4; j++) mx[j>>1] = fmaxf(mx[j>>1], sacc[nt][j]);
    #pragma unroll
    for (int i = 0; i < 2; i++){
        mx[i] = fmaxf(mx[i], __shfl_xor_sync(0xffffffffu, mx[i], 1));
        mx[i] = fmaxf(mx[i], __shfl_xor_sync(0xffffffffu, mx[i], 2));
    }
    float sum[2] = {0.f, 0.f};
    #pragma unroll
    for (int nt = 0; nt < 8; nt++)
        #pragma unroll
        for (int j = 0; j < 4; j++){
            float e = __expf(sacc[nt][j] - mx[j>>1]);
            sacc[nt][j] = e;
            sum[j>>1] += e;
        }
    #pragma unroll
    for (int i = 0; i < 2; i++){
        sum[i] += __shfl_xor_sync(0xffffffffu, sum[i], 1);
        sum[i] += __shfl_xor_sync(0xffffffffu, sum[i], 2);
    }
    float inv[2] = {1.0f/sum[0], 1.0f/sum[1]};

    float oacc[4][4];
    #pragma unroll
    for (int i = 0; i < 4; i++){ oacc[i][0]=0.f; oacc[i][1]=0.f; oacc[i][2]=0.f; oacc[i][3]=0.f; }

    #pragma unroll
    for (int kt2 = 0; kt2 < 4; kt2++){
        uint32_t pa[4];
        pa[0] = packbf(sacc[2*kt2][0],   sacc[2*kt2][1]);
        pa[1] = packbf(sacc[2*kt2][2],   sacc[2*kt2][3]);
        pa[2] = packbf(sacc[2*kt2+1][0], sacc[2*kt2+1][1]);
        pa[3] = packbf(sacc[2*kt2+1][2], sacc[2*kt2+1][3]);
        #pragma unroll
        for (int half = 0; half < 2; half++){
            uint32_t vb[4];
            ldmx4t(vb, swa(Vb, kt2*16 + (lane & 15), half*2 + (lane >> 4)));
            mma_bf16(oacc[2*half],   pa, vb[0], vb[1]);
            mma_bf16(oacc[2*half+1], pa, vb[2], vb[3]);
        }
    }

    #pragma unroll
    for (int i = 0; i < 2; i++){
        int row = r0 + i*8;
        if (row < 49){
            size_t ro = ((size_t)(widx*49 + row))*CCH + hglb*HD;
            #pragma unroll
            for (int nt = 0; nt < 4; nt++){
                __nv_bfloat162 t = __floats2bfloat162_rn(oacc[nt][i*2]*inv[i],
                                                         oacc[nt][i*2+1]*inv[i]);
                *reinterpret_cast<__nv_bfloat162*>(g_o + ro + nt*8 + c2) = t;
            }
        }
    }
}

extern __shared__ __align__(16) char smem_raw[];

// ---------------- kernel: 128x128-tile single-stage GEMM (qkv / fc1), K=128 ----------------
template<int EPI>
__launch_bounds__(256)
__global__ void gemm128_kernel(const float* __restrict__ bias){
    constexpr int LDO = (EPI == 0) ? 384 : 512;
    const __nv_bfloat16* A = (EPI == 0) ? g_xw  : g_ln2;
    const __nv_bfloat16* W = (EPI == 0) ? g_wqkv : g_wfc1;
    __nv_bfloat16* outb    = (EPI == 0) ? g_qkv : g_f1;

    uint4* sA = reinterpret_cast<uint4*>(smem_raw);
    uint4* sB = sA + 2048;

    int tid = threadIdx.x, lane = tid & 31, warp = tid >> 5;
    int wm = warp >> 2, wn = warp & 3;
    int bm = blockIdx.x*128, bn = blockIdx.y*128;

    float acc[4][4][4];
    #pragma unroll
    for (int i = 0; i < 4; i++)
        #pragma unroll
        for (int j = 0; j < 4; j++)
            #pragma unroll
            for (int k = 0; k < 4; k++) acc[i][j][k] = 0.f;

    const __nv_bfloat16* Ag = A + (size_t)bm*128;
    const __nv_bfloat16* Wg = W + (size_t)bn*128;

    #pragma unroll
    for (int j = 0; j < 8; j++){
        int idx = tid + 256*j;
        int r = idx >> 4, u = idx & 15;
        int ph = r*16 + (u ^ (r & 7));
        cp16(sA + ph, Ag + (size_t)r*128 + u*8);
        cp16(sB + ph, Wg + (size_t)r*128 + u*8);
    }
    asm volatile("cp.async.commit_group;");
    asm volatile("cp.async.wait_group 0;");
    __syncthreads();

    auto sw = [](const uint4* base, int row, int unit) -> uint32_t {
        return (uint32_t)__cvta_generic_to_shared(base + row*16 + (unit ^ (row & 7)));
    };
    int arow = (lane & 15), aun = (lane >> 4);
    int brow = (lane & 7) + ((lane >> 4) << 3);
    int bun  = (lane >> 3) & 1;

    #pragma unroll
    for (int ks = 0; ks < 8; ks++){
        uint32_t bfr[2][4];
        ldmx4(bfr[0], sw(sB, wn*32 + brow,      ks*2 + bun));
        ldmx4(bfr[1], sw(sB, wn*32 + brow + 16, ks*2 + bun));
        #pragma unroll
        for (int mt = 0; mt < 4; mt++){
            uint32_t af[4];
            ldmx4(af, sw(sA, wm*64 + mt*16 + arow, ks*2 + aun));
            mma_bf16(acc[mt][0], af, bfr[0][0], bfr[0][1]);
            mma_bf16(acc[mt][1], af, bfr[0][2], bfr[0][3]);
            mma_bf16(acc[mt][2], af, bfr[1][0], bfr[1][1]);
            mma_bf16(acc[mt][3], af, bfr[1][2], bfr[1][3]);
        }
    }

    int l4 = lane >> 2, c2 = (lane & 3)*2;
    #pragma unroll
    for (int mt = 0; mt < 4; mt++){
        int gmb = bm + wm*64 + mt*16 + l4;
        #pragma unroll
        for (int nt = 0; nt < 4; nt++){
            int gn = bn + wn*32 + nt*8 + c2;
            float bv0 = bias[gn], bv1 = bias[gn+1];
            #pragma unroll
            for (int half = 0; half < 2; half++){
                int gm = gmb + half*8;
                float v0 = acc[mt][nt][half*2+0] + bv0;
                float v1 = acc[mt][nt][half*2+1] + bv1;
                if constexpr (EPI == 0){
                    *reinterpret_cast<__nv_bfloat162*>(outb + (size_t)gm*LDO + gn) =
                        __floats2bfloat162_rn(v0, v1);
                } else {
                    *reinterpret_cast<__nv_bfloat162*>(outb + (size_t)gm*LDO + gn) =
                        __floats2bfloat162_rn(gelu_exact(v0), gelu_exact(v1));
                }
            }
        }
    }
}

// ---------------- kernel: proj GEMM 128x128 + scatter + residual + fused LN2 ----------------
__launch_bounds__(256)
__global__ void proj_kernel(const float* __restrict__ bias,
                            const float* __restrict__ resid,
                            const float* __restrict__ g2,
                            const float* __restrict__ b2){
    uint4* sA = reinterpret_cast<uint4*>(smem_raw);
    uint4* sB = sA + 2048;

    int tid = threadIdx.x, lane = tid & 31, warp = tid >> 5;
    int wm = warp >> 2, wn = warp & 3;
    int bm = blockIdx.x*128;

    float acc[4][4][4];
    #pragma unroll
    for (int i = 0; i < 4; i++)
        #pragma unroll
        for (int j = 0; j < 4; j++)
            #pragma unroll
            for (int k = 0; k < 4; k++) acc[i][j][k] = 0.f;

    const __nv_bfloat16* Ag = g_o + (size_t)bm*128;

    #pragma unroll
    for (int j = 0; j < 8; j++){
        int idx = tid + 256*j;
        int r = idx >> 4, u = idx & 15;
        int ph = r*16 + (u ^ (r & 7));
        cp16(sA + ph, Ag + (size_t)r*128 + u*8);
        cp16(sB + ph, g_wproj + (size_t)r*128 + u*8);
    }
    asm volatile("cp.async.commit_group;");
    asm volatile("cp.async.wait_group 0;");
    __syncthreads();

    auto sw = [](const uint4* base, int row, int unit) -> uint32_t {
        return (uint32_t)__cvta_generic_to_shared(base + row*16 + (unit ^ (row & 7)));
    };
    int arow = (lane & 15), aun = (lane >> 4);
    int brow = (lane & 7) + ((lane >> 4) << 3);
    int bun  = (lane >> 3) & 1;

    #pragma unroll
    for (int ks = 0; ks < 8; ks++){
        uint32_t bfr[2][4];
        ldmx4(bfr[0], sw(sB, wn*32 + brow,      ks*2 + bun));
        ldmx4(bfr[1], sw(sB, wn*32 + brow + 16, ks*2 + bun));
        #pragma unroll
        for (int mt = 0; mt < 4; mt++){
            uint32_t af[4];
            ldmx4(af, sw(sA, wm*64 + mt*16 + arow, ks*2 + aun));
            mma_bf16(acc[mt][0], af, bfr[0][0], bfr[0][1]);
            mma_bf16(acc[mt][1], af, bfr[0][2], bfr[0][3]);
            mma_bf16(acc[mt][2], af, bfr[1][0], bfr[1][1]);
            mma_bf16(acc[mt][3], af, bfr[1][2], bfr[1][3]);
        }
    }

    int l4 = lane >> 2, c2 = (lane & 3)*2;
    __syncthreads();
    float* sred = reinterpret_cast<float*>(smem_raw);
    #pragma unroll
    for (int mt = 0; mt < 4; mt++){
        #pragma unroll
        for (int half = 0; half < 2; half++){
            int rloc = wm*64 + mt*16 + l4 + half*8;
            int gm = bm + rloc;
            int p = tok_map(gm);
            float s = 0.f, q = 0.f;
            #pragma unroll
            for (int nt = 0; nt < 4; nt++){
                int gn = wn*32 + nt*8 + c2;
                float2 xr = *reinterpret_cast<const float2*>(resid + (size_t)p*CCH + gn);
                float v0 = acc[mt][nt][half*2+0] + bias[gn]   + xr.x;
                float v1 = acc[mt][nt][half*2+1] + bias[gn+1] + xr.y;
                acc[mt][nt][half*2+0] = v0;
                acc[mt][nt][half*2+1] = v1;
                float2 t; t.x = v0; t.y = v1;
                *reinterpret_cast<float2*>(g_x1 + (size_t)p*CCH + gn) = t;
                s += v0 + v1; q += v0*v0 + v1*v1;
            }
            s += __shfl_xor_sync(0xffffffffu, s, 1);
            s += __shfl_xor_sync(0xffffffffu, s, 2);
            q += __shfl_xor_sync(0xffffffffu, q, 1);
            q += __shfl_xor_sync(0xffffffffu, q, 2);
            if ((lane & 3) == 0){
                sred[rloc*8 + wn]     = s;
                sred[rloc*8 + 4 + wn] = q;
            }
        }
    }
    __syncthreads();
    #pragma unroll
    for (int mt = 0; mt < 4; mt++){
        #pragma unroll
        for (int half = 0; half < 2; half++){
            int rloc = wm*64 + mt*16 + l4 + half*8;
            int gm = bm + rloc;
            int p = tok_map(gm);
            float s = sred[rloc*8+0] + sred[rloc*8+1] + sred[rloc*8+2] + sred[rloc*8+3];
            float q = sred[rloc*8+4] + sred[rloc*8+5] + sred[rloc*8+6] + sred[rloc*8+7];
            float mean = s * (1.0f/CCH);
            float var  = q * (1.0f/CCH) - mean*mean;
            float inv  = rsqrtf(var + 1e-5f);
            #pragma unroll
            for (int nt = 0; nt < 4; nt++){
                int gn = wn*32 + nt*8 + c2;
                float v0 = (acc[mt][nt][half*2+0] - mean)*inv*g2[gn]   + b2[gn];
                float v1 = (acc[mt][nt][half*2+1] - mean)*inv*g2[gn+1] + b2[gn+1];
                *reinterpret_cast<__nv_bfloat162*>(g_ln2 + (size_t)p*CCH + gn) =
                    __floats2bfloat162_rn(v0, v1);
            }
        }
    }
}

// ---------------- kernel: fc2 GEMM (K=512), HMMA 128x64 3-stage ----------------
__launch_bounds__(256, 3)
__global__ void fc2_kernel(const float* __restrict__ bias, float* __restrict__ outf){
    constexpr int KK = 512, KC = 64, U = 8, NC = KK/KC;
    uint4* sbase = reinterpret_cast<uint4*>(smem_raw);
    uint4* sA[3]; uint4* sB[3];
    #pragma unroll
    for (int s = 0; s < 3; s++){
        sA[s] = sbase + s*(128*U + 64*U);
        sB[s] = sA[s] + 128*U;
    }

    int tid = threadIdx.x, lane = tid & 31, warp = tid >> 5;
    int wm = warp >> 1, wn = warp & 1;
    int bm = blockIdx.x*128, bn = blockIdx.y*64;

    float acc[2][4][4];
    #pragma unroll
    for (int i = 0; i < 2; i++)
        #pragma unroll
        for (int j = 0; j < 4; j++)
            #pragma unroll
            for (int k = 0; k < 4; k++) acc[i][j][k] = 0.f;

    const __nv_bfloat16* Ag = g_f1 + (size_t)bm*KK;
    const __nv_bfloat16* Wg = g_wfc2 + (size_t)bn*KK;

    auto stage = [&](int c, int s){
        int kk = c*KC;
        #pragma unroll
        for (int j = 0; j < (128*U)/256; j++){
            int idx = tid + 256*j;
            int r = idx / U, u = idx - r*U;
            cp16(sA[s] + r*U + (u ^ (r & 7)), Ag + (size_t)r*KK + kk + u*8);
        }
        #pragma unroll
        for (int j = 0; j < (64*U)/256; j++){
            int idx = tid + 256*j;
            int r = idx / U, u = idx - r*U;
            cp16(sB[s] + r*U + (u ^ (r & 7)), Wg + (size_t)r*KK + kk + u*8);
        }
    };
    auto sw = [](const uint4* base, int row, int unit) -> uint32_t {
        return (uint32_t)__cvta_generic_to_shared(base + row*U + (unit ^ (row & 7)));
    };

    int arow = (lane & 15), aun = (lane >> 4);
    int brow = (lane & 7) + ((lane >> 4) << 3);
    int bun  = (lane >> 3) & 1;

    auto mma_step = [&](const uint4* sa, const uint4* sb, int ks){
        uint32_t bfr[2][4];
        ldmx4(bfr[0], sw(sb, wn*32 + brow,      ks*2 + bun));
        ldmx4(bfr[1], sw(sb, wn*32 + brow + 16, ks*2 + bun));
        #pragma unroll
        for (int mt = 0; mt < 2; mt++){
            uint32_t af[4];
            ldmx4(af, sw(sa, wm*32 + mt*16 + arow, ks*2 + aun));
            mma_bf16(acc[mt][0], af, bfr[0][0], bfr[0][1]);
            mma_bf16(acc[mt][1], af, bfr[0][2], bfr[0][3]);
            mma_bf16(acc[mt][2], af, bfr[1][0], bfr[1][1]);
            mma_bf16(acc[mt][3], af, bfr[1][2], bfr[1][3]);
        }
    };

    stage(0, 0);
    asm volatile("cp.async.commit_group;");
    stage(1, 1);
    asm volatile("cp.async.commit_group;");
    #pragma unroll
    for (int it = 0; it < NC; it++){
        if (it + 2 < NC){
            stage(it + 2, (it + 2) % 3);
            asm volatile("cp.async.commit_group;");
            asm volatile("cp.async.wait_group 2;");
        } else if (it + 1 < NC){
            asm volatile("cp.async.wait_group 1;");
        } else {
            asm volatile("cp.async.wait_group 0;");
        }
        __syncthreads();
        int s = it % 3;
        #pragma unroll
        for (int ks = 0; ks < KC/16; ks++) mma_step(sA[s], sB[s], ks);
        __syncthreads();
    }

    int l4 = lane >> 2, c2 = (lane & 3)*2;
    #pragma unroll
    for (int mt = 0; mt < 2; mt++){
        int gmb = bm + wm*32 + mt*16 + l4;
        #pragma unroll
        for (int nt = 0; nt < 4; nt++){
            int gn = bn + wn*32 + nt*8 + c2;
            float bv0 = bias[gn], bv1 = bias[gn+1];
            #pragma unroll
            for (int half = 0; half < 2; half++){
                int gm = gmb + half*8;
                size_t o = (size_t)gm*CCH + gn;
                float2 xr = *reinterpret_cast<const float2*>(g_x1 + o);
                float2 t;
                t.x = xr.x + acc[mt][nt][half*2+0] + bv0;
                t.y = xr.y + acc[mt][nt][half*2+1] + bv1;
                *reinterpret_cast<float2*>(outf + o) = t;
            }
        }
    }
}

#define G128_SMEM  65536
#define FC2_SMEM   73728
#define PROJ_SMEM  65536

// ---------------- host launch ----------------
extern "C" void kernel_launch(void* const* d_in, const int* in_sizes, int n_in,
                              void* d_out, int out_size){
    int off = (n_in >= 17) ? 2 : 0;
    const float* x     = (const float*)d_in[0];
    const float* mask  = (const float*)d_in[1 + off];
    const float* ln1g  = (const float*)d_in[2 + off];
    const float* ln1b  = (const float*)d_in[3 + off];
    const float* qkvw  = (const float*)d_in[4 + off];
    const float* qkvb  = (const float*)d_in[5 + off];
    const float* relt  = (const float*)d_in[6 + off];
    const float* projw = (const float*)d_in[7 + off];
    const float* projb = (const float*)d_in[8 + off];
    const float* ln2g  = (const float*)d_in[9 + off];
    const float* ln2b  = (const float*)d_in[10 + off];
    const float* fc1w  = (const float*)d_in[11 + off];
    const float* fc1b  = (const float*)d_in[12 + off];
    const float* fc2w  = (const float*)d_in[13 + off];
    const float* fc2b  = (const float*)d_in[14 + off];
    float* out = (float*)d_out;

    cudaFuncSetAttribute(gemm128_kernel<0>, cudaFuncAttributeMaxDynamicSharedMemorySize, G128_SMEM);
    cudaFuncSetAttribute(gemm128_kernel<1>, cudaFuncAttributeMaxDynamicSharedMemorySize, G128_SMEM);
    cudaFuncSetAttribute(proj_kernel,       cudaFuncAttributeMaxDynamicSharedMemorySize, PROJ_SMEM);
    cudaFuncSetAttribute(fc2_kernel,        cudaFuncAttributeMaxDynamicSharedMemorySize, FC2_SMEM);

    cvt_weights<<<256, 256>>>(qkvw, projw, fc1w, fc2w);
    comb_kernel<<<(NWIMG*NHEAD*64*64 + 255)/256, 256>>>(mask, relt);
    ln1_kernel<<<MTOK/8, 256>>>(x, ln1g, ln1b);
    gemm128_kernel<0><<<dim3(MTOK/128, 3), 256, G128_SMEM>>>(qkvb);
    attn_mma_kernel<<<BWIN*2, 256>>>();
    proj_kernel<<<MTOK/128, 256, PROJ_SMEM>>>(projb, x, ln2g, ln2b);
    gemm128_kernel<1><<<dim3(MTOK/128, 4), 256, G128_SMEM>>>(fc1b);
    fc2_kernel<<<dim3(MTOK/128, 2), 256, FC2_SMEM>>>(fc2b, out);
}